// round 1
// baseline (speedup 1.0000x reference)
#include <cuda_runtime.h>

#define QLEN 512
#define MLEN 512
#define KLEN 1024
#define BSZ 8
#define DMODEL 1024
#define NHEAD 16
#define DHEAD 64
#define DINNER 4096

// ---------------- scratch (no allocations allowed) ----------------
__device__ float g_core[QLEN * BSZ * DMODEL];
__device__ float g_cat[KLEN * BSZ * DMODEL];
__device__ float g_heads[KLEN * BSZ * 3 * DMODEL];
__device__ float g_posemb[KLEN * DMODEL];
__device__ float g_rk[KLEN * DMODEL];
__device__ float g_BDr[BSZ * NHEAD * QLEN * KLEN];
__device__ float g_S[BSZ * NHEAD * QLEN * KLEN];
__device__ float g_attnvec[QLEN * BSZ * DMODEL];
__device__ float g_attnout[QLEN * BSZ * DMODEL];
__device__ float g_h1[QLEN * BSZ * DINNER];
__device__ float g_ff[QLEN * BSZ * DMODEL];

// ---------------- embedding lookup: core = emb[inp] * sqrt(D) ----------------
__global__ void embed_kernel(const int* __restrict__ inp,
                             const float* __restrict__ emb,
                             float* __restrict__ core) {
    int row = blockIdx.x;                 // (i*8 + b)
    int tok = inp[row];
    const float4* src = (const float4*)(emb + (size_t)tok * DMODEL);
    float4* dst = (float4*)(core + (size_t)row * DMODEL);
    float4 v = src[threadIdx.x];
    v.x *= 32.f; v.y *= 32.f; v.z *= 32.f; v.w *= 32.f;
    dst[threadIdx.x] = v;
}

// ---------------- sinusoidal positional embedding ----------------
__global__ void posemb_kernel(float* __restrict__ pe) {
    int k = blockIdx.x;       // 0..1023
    int j = threadIdx.x;      // 0..511
    double invf = exp(-(2.0 * (double)j / 1024.0) * log(10000.0));
    double ang = (double)(KLEN - 1 - k) * invf;
    pe[(size_t)k * DMODEL + j] = (float)sin(ang);
    pe[(size_t)k * DMODEL + 512 + j] = (float)cos(ang);
}

// ---------------- generic NT SGEMM: C[M,N] = A[M,K] * B[N,K]^T (+bias, relu) --
// M%128==0, N%128==0, K%16==0 for all call sites.
template <bool RELU, bool HASBIAS>
__global__ __launch_bounds__(256, 2) void gemm_nt_kernel(
    const float* __restrict__ A, const float* __restrict__ B,
    const float* __restrict__ bias, float* __restrict__ C,
    int M, int N, int K) {
    __shared__ float As[16][132];
    __shared__ float Bs[16][132];
    const int t = threadIdx.x;
    const int tx = t & 15, ty = t >> 4;
    const int m0 = blockIdx.y * 128, n0 = blockIdx.x * 128;
    const int lr = t >> 2;            // 0..63
    const int lc = (t & 3) << 2;      // 0,4,8,12
    const float* Ap = A + (size_t)(m0 + lr) * K + lc;
    const float* Bp = B + (size_t)(n0 + lr) * K + lc;

    float acc[8][8] = {};

    for (int k0 = 0; k0 < K; k0 += 16) {
        float4 a0 = *(const float4*)(Ap + k0);
        float4 a1 = *(const float4*)(Ap + (size_t)64 * K + k0);
        float4 b0 = *(const float4*)(Bp + k0);
        float4 b1 = *(const float4*)(Bp + (size_t)64 * K + k0);
        As[lc + 0][lr] = a0.x; As[lc + 1][lr] = a0.y;
        As[lc + 2][lr] = a0.z; As[lc + 3][lr] = a0.w;
        As[lc + 0][lr + 64] = a1.x; As[lc + 1][lr + 64] = a1.y;
        As[lc + 2][lr + 64] = a1.z; As[lc + 3][lr + 64] = a1.w;
        Bs[lc + 0][lr] = b0.x; Bs[lc + 1][lr] = b0.y;
        Bs[lc + 2][lr] = b0.z; Bs[lc + 3][lr] = b0.w;
        Bs[lc + 0][lr + 64] = b1.x; Bs[lc + 1][lr + 64] = b1.y;
        Bs[lc + 2][lr + 64] = b1.z; Bs[lc + 3][lr + 64] = b1.w;
        __syncthreads();
#pragma unroll
        for (int kk = 0; kk < 16; kk++) {
            float4 aA = *(const float4*)&As[kk][ty * 4];
            float4 aB = *(const float4*)&As[kk][ty * 4 + 64];
            float4 bA = *(const float4*)&Bs[kk][tx * 4];
            float4 bB = *(const float4*)&Bs[kk][tx * 4 + 64];
            float ar[8] = {aA.x, aA.y, aA.z, aA.w, aB.x, aB.y, aB.z, aB.w};
            float br[8] = {bA.x, bA.y, bA.z, bA.w, bB.x, bB.y, bB.z, bB.w};
#pragma unroll
            for (int r = 0; r < 8; r++)
#pragma unroll
                for (int c = 0; c < 8; c++) acc[r][c] += ar[r] * br[c];
        }
        __syncthreads();
    }

    float bv[8];
    if (HASBIAS) {
        float4 x = *(const float4*)(bias + n0 + tx * 4);
        float4 y = *(const float4*)(bias + n0 + tx * 4 + 64);
        bv[0] = x.x; bv[1] = x.y; bv[2] = x.z; bv[3] = x.w;
        bv[4] = y.x; bv[5] = y.y; bv[6] = y.z; bv[7] = y.w;
    } else {
#pragma unroll
        for (int i = 0; i < 8; i++) bv[i] = 0.f;
    }

#pragma unroll
    for (int rh = 0; rh < 2; rh++) {
#pragma unroll
        for (int r = 0; r < 4; r++) {
            float* Cp = C + (size_t)(m0 + rh * 64 + ty * 4 + r) * N + n0;
#pragma unroll
            for (int ch = 0; ch < 2; ch++) {
                float4 o;
                o.x = acc[rh * 4 + r][ch * 4 + 0] + bv[ch * 4 + 0];
                o.y = acc[rh * 4 + r][ch * 4 + 1] + bv[ch * 4 + 1];
                o.z = acc[rh * 4 + r][ch * 4 + 2] + bv[ch * 4 + 2];
                o.w = acc[rh * 4 + r][ch * 4 + 3] + bv[ch * 4 + 3];
                if (RELU) {
                    o.x = fmaxf(o.x, 0.f); o.y = fmaxf(o.y, 0.f);
                    o.z = fmaxf(o.z, 0.f); o.w = fmaxf(o.w, 0.f);
                }
                *(float4*)(Cp + ch * 64 + tx * 4) = o;
            }
        }
    }
}

// ---------------- batched (q+bias)·B^T, 64x64 tiles, K=64 --------------------
// AC mode:  B = k heads (row stride 24576, batch stride 3072)
// BDr mode: B = rk      (row stride 1024,  batch stride 0)
__global__ __launch_bounds__(256) void qk_kernel(
    const float* __restrict__ qbase, const float* __restrict__ bbase,
    const float* __restrict__ bias, float* __restrict__ out,
    int b_batch_stride, int b_row_stride) {
    __shared__ float Qs[64][68];
    __shared__ float Ks[64][68];
    int bh = blockIdx.z;
    int b = bh >> 4, h = bh & 15;
    int i0 = blockIdx.y * 64, j0 = blockIdx.x * 64;
    int t = threadIdx.x;
    const float* qp = qbase + b * 3072 + h * 64;
    const float* bp = bbase + b * b_batch_stride + h * 64;
    const float* bi = bias + h * 64;

#pragma unroll
    for (int l = 0; l < 4; l++) {
        int idx = t + 256 * l;
        int r = idx >> 4;
        int c = (idx & 15) << 2;
        float4 qv = *(const float4*)(qp + (size_t)(i0 + r) * 24576 + c);
        float4 bb = *(const float4*)(bi + c);
        Qs[c + 0][r] = qv.x + bb.x;
        Qs[c + 1][r] = qv.y + bb.y;
        Qs[c + 2][r] = qv.z + bb.z;
        Qs[c + 3][r] = qv.w + bb.w;
        float4 kv = *(const float4*)(bp + (size_t)(j0 + r) * b_row_stride + c);
        Ks[c + 0][r] = kv.x; Ks[c + 1][r] = kv.y;
        Ks[c + 2][r] = kv.z; Ks[c + 3][r] = kv.w;
    }
    __syncthreads();

    int ti = (t >> 4) << 2, tj = (t & 15) << 2;
    float acc[4][4] = {};
#pragma unroll
    for (int d = 0; d < 64; d++) {
        float4 a = *(const float4*)&Qs[d][ti];
        float4 k4 = *(const float4*)&Ks[d][tj];
        float av[4] = {a.x, a.y, a.z, a.w};
        float kv[4] = {k4.x, k4.y, k4.z, k4.w};
#pragma unroll
        for (int r = 0; r < 4; r++)
#pragma unroll
            for (int c = 0; c < 4; c++) acc[r][c] += av[r] * kv[c];
    }

    float* op = out + ((size_t)bh * 512 + i0 + ti) * 1024 + j0 + tj;
#pragma unroll
    for (int r = 0; r < 4; r++) {
        float4 o = {acc[r][0], acc[r][1], acc[r][2], acc[r][3]};
        *(float4*)(op + (size_t)r * 1024) = o;
    }
}

// ---------------- fused rel-shift + mask + scale + softmax (in place) --------
// S holds raw AC.  BD[i,j] = BDr[i, j + 511 - i];  mask: j > i + 512.
__global__ __launch_bounds__(128) void softmax_bd_kernel(
    float* __restrict__ S, const float* __restrict__ BDr) {
    __shared__ float red[128];
    int i = blockIdx.x;
    int bh = blockIdx.y;
    float* row = S + ((size_t)bh * 512 + i) * 1024;
    const float* bd = BDr + ((size_t)bh * 512 + i) * 1024 + (511 - i);
    int t = threadIdx.x;
    int lim = i + 512;

    float v[8];
    float mx = -3e38f;
#pragma unroll
    for (int e = 0; e < 8; e++) {
        int j = t + 128 * e;
        float x = -3e38f;
        if (j <= lim) x = (row[j] + bd[j]) * 0.125f;
        v[e] = x;
        mx = fmaxf(mx, x);
    }
    red[t] = mx;
    __syncthreads();
    for (int s = 64; s > 0; s >>= 1) {
        if (t < s) red[t] = fmaxf(red[t], red[t + s]);
        __syncthreads();
    }
    mx = red[0];
    __syncthreads();

    float sum = 0.f;
#pragma unroll
    for (int e = 0; e < 8; e++) {
        float ex = (v[e] > -1e37f) ? expf(v[e] - mx) : 0.f;
        v[e] = ex;
        sum += ex;
    }
    red[t] = sum;
    __syncthreads();
    for (int s = 64; s > 0; s >>= 1) {
        if (t < s) red[t] += red[t + s];
        __syncthreads();
    }
    float inv = 1.f / red[0];
#pragma unroll
    for (int e = 0; e < 8; e++) row[t + 128 * e] = v[e] * inv;
}

// ---------------- P @ V  (per b,h: 512x64 = P[512x1024] @ V[1024x64]) -------
__global__ __launch_bounds__(256) void pv_kernel(
    const float* __restrict__ P, const float* __restrict__ vbase,
    float* __restrict__ out) {
    __shared__ float Ps[32][132];
    __shared__ float Vs[32][68];
    int bh = blockIdx.y;
    int b = bh >> 4, h = bh & 15;
    int i0 = blockIdx.x * 128;
    const float* prow = P + ((size_t)bh * 512 + i0) * 1024;
    const float* vp = vbase + b * 3072 + h * 64;
    int t = threadIdx.x;
    int ti = (t >> 4) << 3;   // 8 rows
    int td = (t & 15) << 2;   // 4 cols

    float acc[8][4] = {};

    for (int jc = 0; jc < 1024; jc += 32) {
#pragma unroll
        for (int l = 0; l < 4; l++) {
            int idx = t + 256 * l;
            int r = idx >> 3;            // 0..127
            int c = (idx & 7) << 2;      // 0..28
            float4 pv = *(const float4*)(prow + (size_t)r * 1024 + jc + c);
            Ps[c + 0][r] = pv.x; Ps[c + 1][r] = pv.y;
            Ps[c + 2][r] = pv.z; Ps[c + 3][r] = pv.w;
        }
#pragma unroll
        for (int l = 0; l < 2; l++) {
            int idx = t + 256 * l;
            int r = idx >> 4;            // 0..31
            int c = (idx & 15) << 2;     // 0..60
            float4 vv = *(const float4*)(vp + (size_t)(jc + r) * 24576 + c);
            *(float4*)&Vs[r][c] = vv;
        }
        __syncthreads();
#pragma unroll
        for (int j = 0; j < 32; j++) {
            float4 aLo = *(const float4*)&Ps[j][ti];
            float4 aHi = *(const float4*)&Ps[j][ti + 4];
            float4 bv = *(const float4*)&Vs[j][td];
            float av[8] = {aLo.x, aLo.y, aLo.z, aLo.w, aHi.x, aHi.y, aHi.z, aHi.w};
            float bb[4] = {bv.x, bv.y, bv.z, bv.w};
#pragma unroll
            for (int r = 0; r < 8; r++)
#pragma unroll
                for (int c = 0; c < 4; c++) acc[r][c] += av[r] * bb[c];
        }
        __syncthreads();
    }

#pragma unroll
    for (int r = 0; r < 8; r++) {
        float4 o = {acc[r][0], acc[r][1], acc[r][2], acc[r][3]};
        *(float4*)(out + ((size_t)(i0 + ti + r) * 8 + b) * 1024 + h * 64 + td) = o;
    }
}

// ---------------- residual + layernorm: out = LN(x + y) * g + b --------------
__global__ __launch_bounds__(256) void resid_ln_kernel(
    const float* __restrict__ x, const float* __restrict__ y,
    const float* __restrict__ g, const float* __restrict__ bta,
    float* __restrict__ out) {
    __shared__ float red[256];
    int row = blockIdx.x, t = threadIdx.x;
    const float* xr = x + (size_t)row * 1024;
    const float* yr = y + (size_t)row * 1024;
    float v[4];
    float s = 0.f;
#pragma unroll
    for (int e = 0; e < 4; e++) {
        int c = t + 256 * e;
        v[e] = xr[c] + yr[c];
        s += v[e];
    }
    red[t] = s;
    __syncthreads();
    for (int w = 128; w > 0; w >>= 1) {
        if (t < w) red[t] += red[t + w];
        __syncthreads();
    }
    float mean = red[0] * (1.f / 1024.f);
    __syncthreads();
    float s2 = 0.f;
#pragma unroll
    for (int e = 0; e < 4; e++) {
        float d = v[e] - mean;
        s2 += d * d;
    }
    red[t] = s2;
    __syncthreads();
    for (int w = 128; w > 0; w >>= 1) {
        if (t < w) red[t] += red[t + w];
        __syncthreads();
    }
    float inv = rsqrtf(red[0] * (1.f / 1024.f) + 1e-5f);
#pragma unroll
    for (int e = 0; e < 4; e++) {
        int c = t + 256 * e;
        out[(size_t)row * 1024 + c] = (v[e] - mean) * inv * g[c] + bta[c];
    }
}

// ---------------- host orchestration ----------------
extern "C" void kernel_launch(void* const* d_in, const int* in_sizes, int n_in,
                              void* d_out, int out_size) {
    const int* inp = (const int*)d_in[0];
    const float* mems = (const float*)d_in[1];
    const float* emb_table = (const float*)d_in[2];
    const float* r_w_bias = (const float*)d_in[3];
    const float* r_r_bias = (const float*)d_in[4];
    const float* qkv_w = (const float*)d_in[5];
    const float* r_w = (const float*)d_in[6];
    const float* o_w = (const float*)d_in[7];
    const float* ln1_g = (const float*)d_in[8];
    const float* ln1_b = (const float*)d_in[9];
    const float* ff_w1 = (const float*)d_in[10];
    const float* ff_b1 = (const float*)d_in[11];
    const float* ff_w2 = (const float*)d_in[12];
    const float* ff_b2 = (const float*)d_in[13];
    const float* ln2_g = (const float*)d_in[14];
    const float* ln2_b = (const float*)d_in[15];

    void* p;
    cudaGetSymbolAddress(&p, g_core);    float* corep = (float*)p;
    cudaGetSymbolAddress(&p, g_cat);     float* catp = (float*)p;
    cudaGetSymbolAddress(&p, g_heads);   float* headsp = (float*)p;
    cudaGetSymbolAddress(&p, g_posemb);  float* posembp = (float*)p;
    cudaGetSymbolAddress(&p, g_rk);      float* rkp = (float*)p;
    cudaGetSymbolAddress(&p, g_BDr);     float* bdrp = (float*)p;
    cudaGetSymbolAddress(&p, g_S);       float* sp = (float*)p;
    cudaGetSymbolAddress(&p, g_attnvec); float* avecp = (float*)p;
    cudaGetSymbolAddress(&p, g_attnout); float* aoutp = (float*)p;
    cudaGetSymbolAddress(&p, g_h1);      float* h1p = (float*)p;
    cudaGetSymbolAddress(&p, g_ff);      float* ffp = (float*)p;

    const size_t CORE_BYTES = (size_t)QLEN * BSZ * DMODEL * sizeof(float);

    embed_kernel<<<QLEN * BSZ, 256>>>(inp, emb_table, corep);
    posemb_kernel<<<KLEN, 512>>>(posembp);

    for (int l = 0; l < 4; l++) {
        // cat = [mems[l]; core]
        cudaMemcpyAsync(catp, mems + (size_t)l * MLEN * BSZ * DMODEL, CORE_BYTES,
                        cudaMemcpyDeviceToDevice);
        cudaMemcpyAsync(catp + (size_t)MLEN * BSZ * DMODEL, corep, CORE_BYTES,
                        cudaMemcpyDeviceToDevice);
        // heads = cat @ qkv_w[l]^T   (8192 x 3072 x 1024)
        gemm_nt_kernel<false, false><<<dim3(24, 64), 256>>>(
            catp, qkv_w + (size_t)l * 3 * DMODEL * DMODEL, nullptr, headsp,
            KLEN * BSZ, 3 * DMODEL, DMODEL);
        // rk = pos_emb @ r_w[l]^T    (1024 x 1024 x 1024)
        gemm_nt_kernel<false, false><<<dim3(8, 8), 256>>>(
            posembp, r_w + (size_t)l * DMODEL * DMODEL, nullptr, rkp,
            KLEN, DMODEL, DMODEL);
        // BD_raw[b,h,i,u] = (q + r_r_bias) . rk
        qk_kernel<<<dim3(16, 8, 128), 256>>>(
            headsp + (size_t)MLEN * BSZ * 3 * DMODEL, rkp, r_r_bias, bdrp,
            0, DMODEL);
        // AC[b,h,i,j] = (q + r_w_bias) . k
        qk_kernel<<<dim3(16, 8, 128), 256>>>(
            headsp + (size_t)MLEN * BSZ * 3 * DMODEL, headsp + DMODEL,
            r_w_bias, sp, 3 * DMODEL, BSZ * 3 * DMODEL);
        // softmax((AC + shift(BD)) * scale, masked), in place -> P
        softmax_bd_kernel<<<dim3(QLEN, BSZ * NHEAD), 128>>>(sp, bdrp);
        // attn_vec = P @ V
        pv_kernel<<<dim3(4, BSZ * NHEAD), 256>>>(sp, headsp + 2 * DMODEL, avecp);
        // attn_out = attn_vec @ o_w[l]^T   (4096 x 1024 x 1024)
        gemm_nt_kernel<false, false><<<dim3(8, 32), 256>>>(
            avecp, o_w + (size_t)l * DMODEL * DMODEL, nullptr, aoutp,
            QLEN * BSZ, DMODEL, DMODEL);
        // core = LN(core + attn_out)
        resid_ln_kernel<<<QLEN * BSZ, 256>>>(corep, aoutp, ln1_g + l * DMODEL,
                                             ln1_b + l * DMODEL, corep);
        // h1 = relu(core @ ff_w1^T + b1)   (4096 x 4096 x 1024)
        gemm_nt_kernel<true, true><<<dim3(32, 32), 256>>>(
            corep, ff_w1 + (size_t)l * DINNER * DMODEL, ff_b1 + l * DINNER,
            h1p, QLEN * BSZ, DINNER, DMODEL);
        // ff = h1 @ ff_w2^T + b2           (4096 x 1024 x 4096)
        gemm_nt_kernel<false, true><<<dim3(8, 32), 256>>>(
            h1p, ff_w2 + (size_t)l * DMODEL * DINNER, ff_b2 + l * DMODEL,
            ffp, QLEN * BSZ, DMODEL, DINNER);
        // core = LN(core + ff)
        resid_ln_kernel<<<QLEN * BSZ, 256>>>(corep, ffp, ln2_g + l * DMODEL,
                                             ln2_b + l * DMODEL, corep);
    }

    cudaMemcpyAsync(d_out, corep, CORE_BYTES, cudaMemcpyDeviceToDevice);
}

// round 3
// speedup vs baseline: 1.5548x; 1.5548x over previous
#include <cuda_runtime.h>

#define QLEN 512
#define MLEN 512
#define KLEN 1024
#define BSZ 8
#define DMODEL 1024
#define NHEAD 16
#define DHEAD 64
#define DINNER 4096

// ---------------- scratch (no allocations allowed) ----------------
__device__ float g_core[QLEN * BSZ * DMODEL];
__device__ float g_cat[KLEN * BSZ * DMODEL];
__device__ float g_heads[KLEN * BSZ * 3 * DMODEL];
__device__ float g_posemb[KLEN * DMODEL];
__device__ float g_rk[KLEN * DMODEL];
__device__ float g_BDr[BSZ * NHEAD * QLEN * KLEN];
__device__ float g_S[BSZ * NHEAD * QLEN * KLEN];
__device__ float g_attnvec[QLEN * BSZ * DMODEL];
__device__ float g_attnout[QLEN * BSZ * DMODEL];
__device__ float g_h1[QLEN * BSZ * DINNER];
__device__ float g_ff[QLEN * BSZ * DMODEL];

// ---------------- tf32 helpers ----------------
__device__ __forceinline__ unsigned f2tf(float x) {
    unsigned r;
    asm("cvt.rna.tf32.f32 %0, %1;" : "=r"(r) : "f"(x));
    return r;
}

__device__ __forceinline__ void mma8(float* c, const unsigned* a, const unsigned* b) {
    asm volatile(
        "mma.sync.aligned.m16n8k8.row.col.f32.tf32.tf32.f32 "
        "{%0,%1,%2,%3}, {%4,%5,%6,%7}, {%8,%9}, {%0,%1,%2,%3};"
        : "+f"(c[0]), "+f"(c[1]), "+f"(c[2]), "+f"(c[3])
        : "r"(a[0]), "r"(a[1]), "r"(a[2]), "r"(a[3]), "r"(b[0]), "r"(b[1]));
}

// ---------------- embedding lookup: core = emb[inp] * sqrt(D) ----------------
__global__ void embed_kernel(const int* __restrict__ inp,
                             const float* __restrict__ emb,
                             float* __restrict__ core) {
    int row = blockIdx.x;
    int tok = inp[row];
    const float4* src = (const float4*)(emb + (size_t)tok * DMODEL);
    float4* dst = (float4*)(core + (size_t)row * DMODEL);
    float4 v = src[threadIdx.x];
    v.x *= 32.f; v.y *= 32.f; v.z *= 32.f; v.w *= 32.f;
    dst[threadIdx.x] = v;
}

// ---------------- sinusoidal positional embedding ----------------
__global__ void posemb_kernel(float* __restrict__ pe) {
    int k = blockIdx.x;
    int j = threadIdx.x;
    double invf = exp(-(2.0 * (double)j / 1024.0) * log(10000.0));
    double ang = (double)(KLEN - 1 - k) * invf;
    pe[(size_t)k * DMODEL + j] = (float)sin(ang);
    pe[(size_t)k * DMODEL + 512 + j] = (float)cos(ang);
}

// ---------------- NT GEMM via tf32 mma.sync: C[M,N] = A[M,K] B[N,K]^T --------
// CTA tile 128x128, k-tile 32, single static smem buffer + register prefetch.
template <bool RELU, bool HASBIAS>
__global__ __launch_bounds__(256) void gemm_nt_tf32(
    const float* __restrict__ A, const float* __restrict__ B,
    const float* __restrict__ bias, float* __restrict__ C,
    int M, int N, int K) {
    __shared__ unsigned As[128 * 36];
    __shared__ unsigned Bs[128 * 36];
    const int t = threadIdx.x;
    const int m0 = blockIdx.y * 128, n0 = blockIdx.x * 128;
    const int lane = t & 31, wid = t >> 5;
    const int grp = lane >> 2, tq = lane & 3;
    const int wm = (wid & 1) * 64, wn = (wid >> 1) * 32;
    const float* Ab = A + (size_t)m0 * K;
    const float* Bb = B + (size_t)n0 * K;

    int fr[4], fc[4];
#pragma unroll
    for (int i = 0; i < 4; i++) {
        int idx = t + 256 * i;
        fr[i] = idx >> 3;
        fc[i] = (idx & 7) << 2;
    }

    float acc[4][4][4] = {};
    float4 pa[4], pb[4];

#pragma unroll
    for (int i = 0; i < 4; i++) {
        pa[i] = *(const float4*)(Ab + (size_t)fr[i] * K + fc[i]);
        pb[i] = *(const float4*)(Bb + (size_t)fr[i] * K + fc[i]);
    }

    for (int k0 = 0; k0 < K; k0 += 32) {
#pragma unroll
        for (int i = 0; i < 4; i++) {
            *(uint4*)&As[fr[i] * 36 + fc[i]] =
                make_uint4(f2tf(pa[i].x), f2tf(pa[i].y), f2tf(pa[i].z), f2tf(pa[i].w));
            *(uint4*)&Bs[fr[i] * 36 + fc[i]] =
                make_uint4(f2tf(pb[i].x), f2tf(pb[i].y), f2tf(pb[i].z), f2tf(pb[i].w));
        }
        __syncthreads();
        if (k0 + 32 < K) {
#pragma unroll
            for (int i = 0; i < 4; i++) {
                pa[i] = *(const float4*)(Ab + (size_t)fr[i] * K + k0 + 32 + fc[i]);
                pb[i] = *(const float4*)(Bb + (size_t)fr[i] * K + k0 + 32 + fc[i]);
            }
        }
#pragma unroll
        for (int ks = 0; ks < 4; ks++) {
            int k = ks * 8 + tq;
            unsigned af[4][4], bf[4][2];
#pragma unroll
            for (int mi = 0; mi < 4; mi++) {
                int r = wm + mi * 16 + grp;
                af[mi][0] = As[r * 36 + k];
                af[mi][1] = As[(r + 8) * 36 + k];
                af[mi][2] = As[r * 36 + k + 4];
                af[mi][3] = As[(r + 8) * 36 + k + 4];
            }
#pragma unroll
            for (int ni = 0; ni < 4; ni++) {
                int n = wn + ni * 8 + grp;
                bf[ni][0] = Bs[n * 36 + k];
                bf[ni][1] = Bs[n * 36 + k + 4];
            }
#pragma unroll
            for (int mi = 0; mi < 4; mi++)
#pragma unroll
                for (int ni = 0; ni < 4; ni++) mma8(acc[mi][ni], af[mi], bf[ni]);
        }
        __syncthreads();
    }

#pragma unroll
    for (int mi = 0; mi < 4; mi++)
#pragma unroll
        for (int ni = 0; ni < 4; ni++) {
            int col = n0 + wn + ni * 8 + 2 * tq;
            float b0 = 0.f, b1 = 0.f;
            if (HASBIAS) { b0 = __ldg(bias + col); b1 = __ldg(bias + col + 1); }
#pragma unroll
            for (int hh = 0; hh < 2; hh++) {
                int row = m0 + wm + mi * 16 + grp + hh * 8;
                float2 o;
                o.x = acc[mi][ni][hh * 2 + 0] + b0;
                o.y = acc[mi][ni][hh * 2 + 1] + b1;
                if (RELU) { o.x = fmaxf(o.x, 0.f); o.y = fmaxf(o.y, 0.f); }
                *(float2*)(C + (size_t)row * N + col) = o;
            }
        }
}

// ---------------- batched (q+bias)·B^T via tf32 mma, 64x64 tiles, K=64 -------
__global__ __launch_bounds__(256) void qk_tf32(
    const float* __restrict__ qbase, const float* __restrict__ bbase,
    const float* __restrict__ bias, float* __restrict__ out,
    int b_batch_stride, int b_row_stride) {
    __shared__ unsigned Qs[64][68];
    __shared__ unsigned Ks[64][68];
    int bh = blockIdx.z;
    int b = bh >> 4, h = bh & 15;
    int i0 = blockIdx.y * 64, j0 = blockIdx.x * 64;
    int t = threadIdx.x;
    const float* qp = qbase + b * 3072 + h * 64;
    const float* kp = bbase + b * b_batch_stride + h * 64;
    const float* bi = bias + h * 64;

#pragma unroll
    for (int i = 0; i < 4; i++) {
        int idx = t + 256 * i;
        int r = idx >> 4;
        int c = (idx & 15) << 2;
        float4 qv = *(const float4*)(qp + (size_t)(i0 + r) * 24576 + c);
        float4 bb = *(const float4*)(bi + c);
        *(uint4*)&Qs[r][c] = make_uint4(f2tf(qv.x + bb.x), f2tf(qv.y + bb.y),
                                        f2tf(qv.z + bb.z), f2tf(qv.w + bb.w));
        float4 kv = *(const float4*)(kp + (size_t)(j0 + r) * b_row_stride + c);
        *(uint4*)&Ks[r][c] = make_uint4(f2tf(kv.x), f2tf(kv.y), f2tf(kv.z), f2tf(kv.w));
    }
    __syncthreads();

    int lane = t & 31, wid = t >> 5;
    int grp = lane >> 2, tq = lane & 3;
    int wm = (wid & 1) * 32, wn = (wid >> 1) * 16;
    float acc[2][2][4] = {};

#pragma unroll
    for (int ks = 0; ks < 8; ks++) {
        int k = ks * 8 + tq;
        unsigned af[2][4], bf[2][2];
#pragma unroll
        for (int mi = 0; mi < 2; mi++) {
            int r = wm + mi * 16 + grp;
            af[mi][0] = Qs[r][k];
            af[mi][1] = Qs[r + 8][k];
            af[mi][2] = Qs[r][k + 4];
            af[mi][3] = Qs[r + 8][k + 4];
        }
#pragma unroll
        for (int ni = 0; ni < 2; ni++) {
            int n = wn + ni * 8 + grp;
            bf[ni][0] = Ks[n][k];
            bf[ni][1] = Ks[n][k + 4];
        }
#pragma unroll
        for (int mi = 0; mi < 2; mi++)
#pragma unroll
            for (int ni = 0; ni < 2; ni++) mma8(acc[mi][ni], af[mi], bf[ni]);
    }

#pragma unroll
    for (int mi = 0; mi < 2; mi++)
#pragma unroll
        for (int ni = 0; ni < 2; ni++)
#pragma unroll
            for (int hh = 0; hh < 2; hh++) {
                int row = i0 + wm + mi * 16 + grp + hh * 8;
                int col = j0 + wn + ni * 8 + 2 * tq;
                float2 o = {acc[mi][ni][hh * 2], acc[mi][ni][hh * 2 + 1]};
                *(float2*)(out + ((size_t)bh * 512 + row) * 1024 + col) = o;
            }
}

// ---------------- fused rel-shift + mask + scale + softmax (in place) --------
__global__ __launch_bounds__(128) void softmax_bd_kernel(
    float* __restrict__ S, const float* __restrict__ BDr) {
    __shared__ float red[128];
    int i = blockIdx.x;
    int bh = blockIdx.y;
    float* row = S + ((size_t)bh * 512 + i) * 1024;
    const float* bd = BDr + ((size_t)bh * 512 + i) * 1024 + (511 - i);
    int t = threadIdx.x;
    int lim = i + 512;

    float v[8];
    float mx = -3e38f;
#pragma unroll
    for (int e = 0; e < 8; e++) {
        int j = t + 128 * e;
        float x = -3e38f;
        if (j <= lim) x = (row[j] + bd[j]) * 0.125f;
        v[e] = x;
        mx = fmaxf(mx, x);
    }
    red[t] = mx;
    __syncthreads();
    for (int s = 64; s > 0; s >>= 1) {
        if (t < s) red[t] = fmaxf(red[t], red[t + s]);
        __syncthreads();
    }
    mx = red[0];
    __syncthreads();

    float sum = 0.f;
#pragma unroll
    for (int e = 0; e < 8; e++) {
        float ex = (v[e] > -1e37f) ? expf(v[e] - mx) : 0.f;
        v[e] = ex;
        sum += ex;
    }
    red[t] = sum;
    __syncthreads();
    for (int s = 64; s > 0; s >>= 1) {
        if (t < s) red[t] += red[t + s];
        __syncthreads();
    }
    float inv = 1.f / red[0];
#pragma unroll
    for (int e = 0; e < 8; e++) row[t + 128 * e] = v[e] * inv;
}

// ---------------- P @ V via tf32 mma (per b,h: 512x64, K=1024) ---------------
__global__ __launch_bounds__(256) void pv_tf32(
    const float* __restrict__ P, const float* __restrict__ vbase,
    float* __restrict__ out) {
    __shared__ unsigned Ps[128][36];
    __shared__ unsigned Vs[32][72];
    int bh = blockIdx.y;
    int b = bh >> 4, h = bh & 15;
    int i0 = blockIdx.x * 128;
    const float* prow = P + ((size_t)bh * 512 + i0) * 1024;
    const float* vp = vbase + b * 3072 + h * 64;
    int t = threadIdx.x;
    int lane = t & 31, wid = t >> 5;
    int grp = lane >> 2, tq = lane & 3;
    int wm = (wid & 3) * 32, wn = (wid >> 2) * 32;
    float acc[2][4][4] = {};

    for (int jc = 0; jc < 1024; jc += 32) {
#pragma unroll
        for (int i = 0; i < 4; i++) {
            int idx = t + 256 * i;
            int r = idx >> 3;
            int c = (idx & 7) << 2;
            float4 p4 = *(const float4*)(prow + (size_t)r * 1024 + jc + c);
            *(uint4*)&Ps[r][c] = make_uint4(f2tf(p4.x), f2tf(p4.y), f2tf(p4.z), f2tf(p4.w));
        }
#pragma unroll
        for (int i = 0; i < 2; i++) {
            int idx = t + 256 * i;
            int r = idx >> 4;
            int c = (idx & 15) << 2;
            float4 vv = *(const float4*)(vp + (size_t)(jc + r) * 24576 + c);
            *(uint4*)&Vs[r][c] = make_uint4(f2tf(vv.x), f2tf(vv.y), f2tf(vv.z), f2tf(vv.w));
        }
        __syncthreads();
#pragma unroll
        for (int ks = 0; ks < 4; ks++) {
            int k = ks * 8 + tq;
            unsigned af[2][4], bf[4][2];
#pragma unroll
            for (int mi = 0; mi < 2; mi++) {
                int r = wm + mi * 16 + grp;
                af[mi][0] = Ps[r][k];
                af[mi][1] = Ps[r + 8][k];
                af[mi][2] = Ps[r][k + 4];
                af[mi][3] = Ps[r + 8][k + 4];
            }
#pragma unroll
            for (int ni = 0; ni < 4; ni++) {
                int n = wn + ni * 8 + grp;
                bf[ni][0] = Vs[k][n];
                bf[ni][1] = Vs[k + 4][n];
            }
#pragma unroll
            for (int mi = 0; mi < 2; mi++)
#pragma unroll
                for (int ni = 0; ni < 4; ni++) mma8(acc[mi][ni], af[mi], bf[ni]);
        }
        __syncthreads();
    }

#pragma unroll
    for (int mi = 0; mi < 2; mi++)
#pragma unroll
        for (int ni = 0; ni < 4; ni++)
#pragma unroll
            for (int hh = 0; hh < 2; hh++) {
                int row = i0 + wm + mi * 16 + grp + hh * 8;
                int col = wn + ni * 8 + 2 * tq;
                float2 o = {acc[mi][ni][hh * 2], acc[mi][ni][hh * 2 + 1]};
                *(float2*)(out + ((size_t)row * 8 + b) * 1024 + h * 64 + col) = o;
            }
}

// ---------------- residual + layernorm: out = LN(x + y) * g + b --------------
__global__ __launch_bounds__(256) void resid_ln_kernel(
    const float* __restrict__ x, const float* __restrict__ y,
    const float* __restrict__ g, const float* __restrict__ bta,
    float* __restrict__ out) {
    __shared__ float red[256];
    int row = blockIdx.x, t = threadIdx.x;
    const float* xr = x + (size_t)row * 1024;
    const float* yr = y + (size_t)row * 1024;
    float v[4];
    float s = 0.f;
#pragma unroll
    for (int e = 0; e < 4; e++) {
        int c = t + 256 * e;
        v[e] = xr[c] + yr[c];
        s += v[e];
    }
    red[t] = s;
    __syncthreads();
    for (int w = 128; w > 0; w >>= 1) {
        if (t < w) red[t] += red[t + w];
        __syncthreads();
    }
    float mean = red[0] * (1.f / 1024.f);
    __syncthreads();
    float s2 = 0.f;
#pragma unroll
    for (int e = 0; e < 4; e++) {
        float d = v[e] - mean;
        s2 += d * d;
    }
    red[t] = s2;
    __syncthreads();
    for (int w = 128; w > 0; w >>= 1) {
        if (t < w) red[t] += red[t + w];
        __syncthreads();
    }
    float inv = rsqrtf(red[0] * (1.f / 1024.f) + 1e-5f);
#pragma unroll
    for (int e = 0; e < 4; e++) {
        int c = t + 256 * e;
        out[(size_t)row * 1024 + c] = (v[e] - mean) * inv * g[c] + bta[c];
    }
}

// ---------------- host orchestration ----------------
extern "C" void kernel_launch(void* const* d_in, const int* in_sizes, int n_in,
                              void* d_out, int out_size) {
    const int* inp = (const int*)d_in[0];
    const float* mems = (const float*)d_in[1];
    const float* emb_table = (const float*)d_in[2];
    const float* r_w_bias = (const float*)d_in[3];
    const float* r_r_bias = (const float*)d_in[4];
    const float* qkv_w = (const float*)d_in[5];
    const float* r_w = (const float*)d_in[6];
    const float* o_w = (const float*)d_in[7];
    const float* ln1_g = (const float*)d_in[8];
    const float* ln1_b = (const float*)d_in[9];
    const float* ff_w1 = (const float*)d_in[10];
    const float* ff_b1 = (const float*)d_in[11];
    const float* ff_w2 = (const float*)d_in[12];
    const float* ff_b2 = (const float*)d_in[13];
    const float* ln2_g = (const float*)d_in[14];
    const float* ln2_b = (const float*)d_in[15];

    void* p;
    cudaGetSymbolAddress(&p, g_core);    float* corep = (float*)p;
    cudaGetSymbolAddress(&p, g_cat);     float* catp = (float*)p;
    cudaGetSymbolAddress(&p, g_heads);   float* headsp = (float*)p;
    cudaGetSymbolAddress(&p, g_posemb);  float* posembp = (float*)p;
    cudaGetSymbolAddress(&p, g_rk);      float* rkp = (float*)p;
    cudaGetSymbolAddress(&p, g_BDr);     float* bdrp = (float*)p;
    cudaGetSymbolAddress(&p, g_S);       float* sp = (float*)p;
    cudaGetSymbolAddress(&p, g_attnvec); float* avecp = (float*)p;
    cudaGetSymbolAddress(&p, g_attnout); float* aoutp = (float*)p;
    cudaGetSymbolAddress(&p, g_h1);      float* h1p = (float*)p;
    cudaGetSymbolAddress(&p, g_ff);      float* ffp = (float*)p;

    const size_t CORE_BYTES = (size_t)QLEN * BSZ * DMODEL * sizeof(float);

    embed_kernel<<<QLEN * BSZ, 256>>>(inp, emb_table, corep);
    posemb_kernel<<<KLEN, 512>>>(posembp);

    for (int l = 0; l < 4; l++) {
        cudaMemcpyAsync(catp, mems + (size_t)l * MLEN * BSZ * DMODEL, CORE_BYTES,
                        cudaMemcpyDeviceToDevice);
        cudaMemcpyAsync(catp + (size_t)MLEN * BSZ * DMODEL, corep, CORE_BYTES,
                        cudaMemcpyDeviceToDevice);
        // heads = cat @ qkv_w[l]^T   (8192 x 3072 x 1024)
        gemm_nt_tf32<false, false><<<dim3(24, 64), 256>>>(
            catp, qkv_w + (size_t)l * 3 * DMODEL * DMODEL, nullptr, headsp,
            KLEN * BSZ, 3 * DMODEL, DMODEL);
        // rk = pos_emb @ r_w[l]^T    (1024 x 1024 x 1024)
        gemm_nt_tf32<false, false><<<dim3(8, 8), 256>>>(
            posembp, r_w + (size_t)l * DMODEL * DMODEL, nullptr, rkp,
            KLEN, DMODEL, DMODEL);
        // BD_raw = (q + r_r_bias) . rk
        qk_tf32<<<dim3(16, 8, 128), 256>>>(
            headsp + (size_t)MLEN * BSZ * 3 * DMODEL, rkp, r_r_bias, bdrp,
            0, DMODEL);
        // AC = (q + r_w_bias) . k
        qk_tf32<<<dim3(16, 8, 128), 256>>>(
            headsp + (size_t)MLEN * BSZ * 3 * DMODEL, headsp + DMODEL,
            r_w_bias, sp, 3 * DMODEL, BSZ * 3 * DMODEL);
        // softmax((AC + shift(BD)) * scale, masked) in place -> P
        softmax_bd_kernel<<<dim3(QLEN, BSZ * NHEAD), 128>>>(sp, bdrp);
        // attn_vec = P @ V
        pv_tf32<<<dim3(4, BSZ * NHEAD), 256>>>(sp, headsp + 2 * DMODEL, avecp);
        // attn_out = attn_vec @ o_w[l]^T   (4096 x 1024 x 1024)
        gemm_nt_tf32<false, false><<<dim3(8, 32), 256>>>(
            avecp, o_w + (size_t)l * DMODEL * DMODEL, nullptr, aoutp,
            QLEN * BSZ, DMODEL, DMODEL);
        resid_ln_kernel<<<QLEN * BSZ, 256>>>(corep, aoutp, ln1_g + l * DMODEL,
                                             ln1_b + l * DMODEL, corep);
        // h1 = relu(core @ ff_w1^T + b1)   (4096 x 4096 x 1024)
        gemm_nt_tf32<true, true><<<dim3(32, 32), 256>>>(
            corep, ff_w1 + (size_t)l * DINNER * DMODEL, ff_b1 + l * DINNER,
            h1p, QLEN * BSZ, DINNER, DMODEL);
        // ff = h1 @ ff_w2^T + b2           (4096 x 1024 x 4096)
        gemm_nt_tf32<false, true><<<dim3(8, 32), 256>>>(
            h1p, ff_w2 + (size_t)l * DMODEL * DINNER, ff_b2 + l * DMODEL,
            ffp, QLEN * BSZ, DMODEL, DINNER);
        resid_ln_kernel<<<QLEN * BSZ, 256>>>(corep, ffp, ln2_g + l * DMODEL,
                                             ln2_b + l * DMODEL, corep);
    }

    cudaMemcpyAsync(d_out, corep, CORE_BYTES, cudaMemcpyDeviceToDevice);
}

// round 4
// speedup vs baseline: 2.5412x; 1.6344x over previous
#include <cuda_runtime.h>

#define QLEN 512
#define MLEN 512
#define KLEN 1024
#define BSZ 8
#define DMODEL 1024
#define NHEAD 16
#define DHEAD 64
#define DINNER 4096

// ---------------- scratch (no allocations allowed) ----------------
__device__ float g_core[QLEN * BSZ * DMODEL];
__device__ float g_cat[KLEN * BSZ * DMODEL];
__device__ float g_heads[KLEN * BSZ * 3 * DMODEL];
__device__ float g_posemb[KLEN * DMODEL];
__device__ float g_rk[KLEN * DMODEL];
__device__ float g_BDr[BSZ * NHEAD * QLEN * KLEN];
__device__ float g_attnvec[QLEN * BSZ * DMODEL];
__device__ float g_attnout[QLEN * BSZ * DMODEL];
__device__ float g_h1[QLEN * BSZ * DINNER];
__device__ float g_ff[QLEN * BSZ * DMODEL];

// ---------------- tf32 helpers ----------------
__device__ __forceinline__ unsigned f2tf(float x) {
    unsigned r;
    asm("cvt.rna.tf32.f32 %0, %1;" : "=r"(r) : "f"(x));
    return r;
}

__device__ __forceinline__ void mma8(float* c, const unsigned* a, const unsigned* b) {
    asm volatile(
        "mma.sync.aligned.m16n8k8.row.col.f32.tf32.tf32.f32 "
        "{%0,%1,%2,%3}, {%4,%5,%6,%7}, {%8,%9}, {%0,%1,%2,%3};"
        : "+f"(c[0]), "+f"(c[1]), "+f"(c[2]), "+f"(c[3])
        : "r"(a[0]), "r"(a[1]), "r"(a[2]), "r"(a[3]), "r"(b[0]), "r"(b[1]));
}

// ---------------- embedding lookup: core = emb[inp] * sqrt(D) ----------------
__global__ void embed_kernel(const int* __restrict__ inp,
                             const float* __restrict__ emb,
                             float* __restrict__ core) {
    int row = blockIdx.x;
    int tok = inp[row];
    const float4* src = (const float4*)(emb + (size_t)tok * DMODEL);
    float4* dst = (float4*)(core + (size_t)row * DMODEL);
    float4 v = src[threadIdx.x];
    v.x *= 32.f; v.y *= 32.f; v.z *= 32.f; v.w *= 32.f;
    dst[threadIdx.x] = v;
}

// ---------------- sinusoidal positional embedding ----------------
__global__ void posemb_kernel(float* __restrict__ pe) {
    int k = blockIdx.x;
    int j = threadIdx.x;
    double invf = exp(-(2.0 * (double)j / 1024.0) * log(10000.0));
    double ang = (double)(KLEN - 1 - k) * invf;
    pe[(size_t)k * DMODEL + j] = (float)sin(ang);
    pe[(size_t)k * DMODEL + 512 + j] = (float)cos(ang);
}

// ---------------- NT GEMM via tf32 mma.sync: C[M,N] = A[M,K] B[N,K]^T --------
template <bool RELU, bool HASBIAS>
__global__ __launch_bounds__(256, 2) void gemm_nt_tf32(
    const float* __restrict__ A, const float* __restrict__ B,
    const float* __restrict__ bias, float* __restrict__ C,
    int M, int N, int K) {
    __shared__ unsigned As[128 * 36];
    __shared__ unsigned Bs[128 * 36];
    const int t = threadIdx.x;
    const int m0 = blockIdx.y * 128, n0 = blockIdx.x * 128;
    const int lane = t & 31, wid = t >> 5;
    const int grp = lane >> 2, tq = lane & 3;
    const int wm = (wid & 1) * 64, wn = (wid >> 1) * 32;
    const float* Ab = A + (size_t)m0 * K;
    const float* Bb = B + (size_t)n0 * K;

    int fr[4], fc[4];
#pragma unroll
    for (int i = 0; i < 4; i++) {
        int idx = t + 256 * i;
        fr[i] = idx >> 3;
        fc[i] = (idx & 7) << 2;
    }

    float acc[4][4][4] = {};
    float4 pa[4], pb[4];

#pragma unroll
    for (int i = 0; i < 4; i++) {
        pa[i] = *(const float4*)(Ab + (size_t)fr[i] * K + fc[i]);
        pb[i] = *(const float4*)(Bb + (size_t)fr[i] * K + fc[i]);
    }

    for (int k0 = 0; k0 < K; k0 += 32) {
#pragma unroll
        for (int i = 0; i < 4; i++) {
            *(uint4*)&As[fr[i] * 36 + fc[i]] =
                make_uint4(f2tf(pa[i].x), f2tf(pa[i].y), f2tf(pa[i].z), f2tf(pa[i].w));
            *(uint4*)&Bs[fr[i] * 36 + fc[i]] =
                make_uint4(f2tf(pb[i].x), f2tf(pb[i].y), f2tf(pb[i].z), f2tf(pb[i].w));
        }
        __syncthreads();
        if (k0 + 32 < K) {
#pragma unroll
            for (int i = 0; i < 4; i++) {
                pa[i] = *(const float4*)(Ab + (size_t)fr[i] * K + k0 + 32 + fc[i]);
                pb[i] = *(const float4*)(Bb + (size_t)fr[i] * K + k0 + 32 + fc[i]);
            }
        }
#pragma unroll
        for (int ks = 0; ks < 4; ks++) {
            int k = ks * 8 + tq;
            unsigned af[4][4], bf[4][2];
#pragma unroll
            for (int mi = 0; mi < 4; mi++) {
                int r = wm + mi * 16 + grp;
                af[mi][0] = As[r * 36 + k];
                af[mi][1] = As[(r + 8) * 36 + k];
                af[mi][2] = As[r * 36 + k + 4];
                af[mi][3] = As[(r + 8) * 36 + k + 4];
            }
#pragma unroll
            for (int ni = 0; ni < 4; ni++) {
                int n = wn + ni * 8 + grp;
                bf[ni][0] = Bs[n * 36 + k];
                bf[ni][1] = Bs[n * 36 + k + 4];
            }
#pragma unroll
            for (int mi = 0; mi < 4; mi++)
#pragma unroll
                for (int ni = 0; ni < 4; ni++) mma8(acc[mi][ni], af[mi], bf[ni]);
        }
        __syncthreads();
    }

#pragma unroll
    for (int mi = 0; mi < 4; mi++)
#pragma unroll
        for (int ni = 0; ni < 4; ni++) {
            int col = n0 + wn + ni * 8 + 2 * tq;
            float b0 = 0.f, b1 = 0.f;
            if (HASBIAS) { b0 = __ldg(bias + col); b1 = __ldg(bias + col + 1); }
#pragma unroll
            for (int hh = 0; hh < 2; hh++) {
                int row = m0 + wm + mi * 16 + grp + hh * 8;
                float2 o;
                o.x = acc[mi][ni][hh * 2 + 0] + b0;
                o.y = acc[mi][ni][hh * 2 + 1] + b1;
                if (RELU) { o.x = fmaxf(o.x, 0.f); o.y = fmaxf(o.y, 0.f); }
                *(float2*)(C + (size_t)row * N + col) = o;
            }
        }
}

// ---------------- batched (q+bias)·B^T via tf32 mma, 64x64 tiles, K=64 -------
// Used only for BDr = (q + r_r_bias) · rk
__global__ __launch_bounds__(256) void qk_tf32(
    const float* __restrict__ qbase, const float* __restrict__ bbase,
    const float* __restrict__ bias, float* __restrict__ out,
    int b_batch_stride, int b_row_stride) {
    __shared__ unsigned Qs[64][68];
    __shared__ unsigned Ks[64][68];
    int bh = blockIdx.z;
    int b = bh >> 4, h = bh & 15;
    int i0 = blockIdx.y * 64, j0 = blockIdx.x * 64;
    int t = threadIdx.x;
    const float* qp = qbase + b * 3072 + h * 64;
    const float* kp = bbase + b * b_batch_stride + h * 64;
    const float* bi = bias + h * 64;

#pragma unroll
    for (int i = 0; i < 4; i++) {
        int idx = t + 256 * i;
        int r = idx >> 4;
        int c = (idx & 15) << 2;
        float4 qv = *(const float4*)(qp + (size_t)(i0 + r) * 24576 + c);
        float4 bb = *(const float4*)(bi + c);
        *(uint4*)&Qs[r][c] = make_uint4(f2tf(qv.x + bb.x), f2tf(qv.y + bb.y),
                                        f2tf(qv.z + bb.z), f2tf(qv.w + bb.w));
        float4 kv = *(const float4*)(kp + (size_t)(j0 + r) * b_row_stride + c);
        *(uint4*)&Ks[r][c] = make_uint4(f2tf(kv.x), f2tf(kv.y), f2tf(kv.z), f2tf(kv.w));
    }
    __syncthreads();

    int lane = t & 31, wid = t >> 5;
    int grp = lane >> 2, tq = lane & 3;
    int wm = (wid & 1) * 32, wn = (wid >> 1) * 16;
    float acc[2][2][4] = {};

#pragma unroll
    for (int ks = 0; ks < 8; ks++) {
        int k = ks * 8 + tq;
        unsigned af[2][4], bf[2][2];
#pragma unroll
        for (int mi = 0; mi < 2; mi++) {
            int r = wm + mi * 16 + grp;
            af[mi][0] = Qs[r][k];
            af[mi][1] = Qs[r + 8][k];
            af[mi][2] = Qs[r][k + 4];
            af[mi][3] = Qs[r + 8][k + 4];
        }
#pragma unroll
        for (int ni = 0; ni < 2; ni++) {
            int n = wn + ni * 8 + grp;
            bf[ni][0] = Ks[n][k];
            bf[ni][1] = Ks[n][k + 4];
        }
#pragma unroll
        for (int mi = 0; mi < 2; mi++)
#pragma unroll
            for (int ni = 0; ni < 2; ni++) mma8(acc[mi][ni], af[mi], bf[ni]);
    }

#pragma unroll
    for (int mi = 0; mi < 2; mi++)
#pragma unroll
        for (int ni = 0; ni < 2; ni++)
#pragma unroll
            for (int hh = 0; hh < 2; hh++) {
                int row = i0 + wm + mi * 16 + grp + hh * 8;
                int col = j0 + wn + ni * 8 + 2 * tq;
                float2 o = {acc[mi][ni][hh * 2], acc[mi][ni][hh * 2 + 1]};
                *(float2*)(out + ((size_t)bh * 512 + row) * 1024 + col) = o;
            }
}

// ---------------- flash attention: AC + BDr-gather + online softmax + PV -----
// Block: 128 threads (4 warps), each warp owns 16 query rows.
// Per block: 64 query rows (i0..i0+63) of one (b,h); loop over 32-wide j tiles.
__global__ __launch_bounds__(128) void flash_attn(
    const float* __restrict__ qbase, const float* __restrict__ kbase,
    const float* __restrict__ vbase, const float* __restrict__ BDr,
    const float* __restrict__ rwb, float* __restrict__ out) {
    __shared__ unsigned sQ[64 * 68];   // Q + r_w_bias (tf32), [64 rows][64 d]
    __shared__ unsigned sKP[64 * 36];  // phase A: K [32 j][64 d] stride 68; phase B: P [64 i][32 j] stride 36
    __shared__ unsigned sV[32 * 72];   // V [32 j][64 d]

    const int i0 = blockIdx.x * 64;
    const int bh = blockIdx.y;
    const int b = bh >> 4, h = bh & 15;
    const int t = threadIdx.x;
    const int lane = t & 31;
    const int wid = t >> 5;
    const int grp = lane >> 2, tq = lane & 3;
    const int wm = wid * 16;

    const float* qp = qbase + b * 3072 + h * 64;
    const float* kp = kbase + b * 3072 + h * 64;
    const float* vp = vbase + b * 3072 + h * 64;
    const float* bdp = BDr + (size_t)bh * QLEN * KLEN;

    // load Q + r_w_bias
#pragma unroll
    for (int i = 0; i < 8; i++) {
        int f = t + 128 * i;     // 0..1023
        int r = f >> 4;          // 0..63
        int c = (f & 15) << 2;   // 0..60
        float4 qv = *(const float4*)(qp + (size_t)(i0 + r) * 24576 + c);
        float4 bb = *(const float4*)(rwb + h * 64 + c);
        sQ[r * 68 + c + 0] = f2tf(qv.x + bb.x);
        sQ[r * 68 + c + 1] = f2tf(qv.y + bb.y);
        sQ[r * 68 + c + 2] = f2tf(qv.z + bb.z);
        sQ[r * 68 + c + 3] = f2tf(qv.w + bb.w);
    }

    const int r0g = i0 + wm + grp;   // global query row for acc vals 0,1
    const int r1g = r0g + 8;         // for vals 2,3
    float m0 = -3e38f, m1 = -3e38f, l0 = 0.f, l1 = 0.f;
    float oacc[8][4] = {};

    const int njt = (i0 + 576) >> 5;
    for (int jt = 0; jt < njt; jt++) {
        const int j0 = jt * 32;
        __syncthreads();  // prior readers of sKP/sV done (also covers sQ on iter 0)
        // load K, V tiles (32 x 64)
#pragma unroll
        for (int i = 0; i < 4; i++) {
            int f = t + 128 * i;   // 0..511
            int r = f >> 4;        // 0..31
            int c = (f & 15) << 2;
            float4 kv = *(const float4*)(kp + (size_t)(j0 + r) * 24576 + c);
            sKP[r * 68 + c + 0] = f2tf(kv.x);
            sKP[r * 68 + c + 1] = f2tf(kv.y);
            sKP[r * 68 + c + 2] = f2tf(kv.z);
            sKP[r * 68 + c + 3] = f2tf(kv.w);
            float4 vv = *(const float4*)(vp + (size_t)(j0 + r) * 24576 + c);
            sV[r * 72 + c + 0] = f2tf(vv.x);
            sV[r * 72 + c + 1] = f2tf(vv.y);
            sV[r * 72 + c + 2] = f2tf(vv.z);
            sV[r * 72 + c + 3] = f2tf(vv.w);
        }
        __syncthreads();

        // AC = Qw . K^T  (warp: 16 rows x 32 cols)
        float sacc[4][4] = {};
#pragma unroll
        for (int ks = 0; ks < 8; ks++) {
            int k = ks * 8 + tq;
            unsigned a[4];
            a[0] = sQ[(wm + grp) * 68 + k];
            a[1] = sQ[(wm + grp + 8) * 68 + k];
            a[2] = sQ[(wm + grp) * 68 + k + 4];
            a[3] = sQ[(wm + grp + 8) * 68 + k + 4];
#pragma unroll
            for (int ni = 0; ni < 4; ni++) {
                unsigned bfr[2];
                bfr[0] = sKP[(ni * 8 + grp) * 68 + k];
                bfr[1] = sKP[(ni * 8 + grp) * 68 + k + 4];
                mma8(sacc[ni], a, bfr);
            }
        }

        // gather shifted BDr, scale, mask
        float sv[4][4];
#pragma unroll
        for (int ni = 0; ni < 4; ni++)
#pragma unroll
            for (int v = 0; v < 4; v++) {
                int jg = j0 + ni * 8 + 2 * tq + (v & 1);
                int ig = (v < 2) ? r0g : r1g;
                float x = -3e38f;
                if (jg <= ig + 512) {
                    float bd = __ldg(bdp + (size_t)ig * KLEN + (jg + 511 - ig));
                    x = (sacc[ni][v] + bd) * 0.125f;
                }
                sv[ni][v] = x;
            }

        // warp-local online softmax (rows r0g, r1g owned by quad lanes)
        float rm0 = -3e38f, rm1 = -3e38f;
#pragma unroll
        for (int ni = 0; ni < 4; ni++) {
            rm0 = fmaxf(rm0, fmaxf(sv[ni][0], sv[ni][1]));
            rm1 = fmaxf(rm1, fmaxf(sv[ni][2], sv[ni][3]));
        }
        rm0 = fmaxf(rm0, __shfl_xor_sync(0xffffffff, rm0, 1));
        rm0 = fmaxf(rm0, __shfl_xor_sync(0xffffffff, rm0, 2));
        rm1 = fmaxf(rm1, __shfl_xor_sync(0xffffffff, rm1, 1));
        rm1 = fmaxf(rm1, __shfl_xor_sync(0xffffffff, rm1, 2));
        float mn0 = fmaxf(m0, rm0), mn1 = fmaxf(m1, rm1);
        float c0 = exp2f((m0 - mn0) * 1.44269504f);
        float c1 = exp2f((m1 - mn1) * 1.44269504f);
        float rs0 = 0.f, rs1 = 0.f;
#pragma unroll
        for (int ni = 0; ni < 4; ni++) {
            sv[ni][0] = exp2f((sv[ni][0] - mn0) * 1.44269504f);
            sv[ni][1] = exp2f((sv[ni][1] - mn0) * 1.44269504f);
            sv[ni][2] = exp2f((sv[ni][2] - mn1) * 1.44269504f);
            sv[ni][3] = exp2f((sv[ni][3] - mn1) * 1.44269504f);
            rs0 += sv[ni][0] + sv[ni][1];
            rs1 += sv[ni][2] + sv[ni][3];
        }
        rs0 += __shfl_xor_sync(0xffffffff, rs0, 1);
        rs0 += __shfl_xor_sync(0xffffffff, rs0, 2);
        rs1 += __shfl_xor_sync(0xffffffff, rs1, 1);
        rs1 += __shfl_xor_sync(0xffffffff, rs1, 2);
        l0 = l0 * c0 + rs0;
        l1 = l1 * c1 + rs1;
        m0 = mn0; m1 = mn1;
#pragma unroll
        for (int ni = 0; ni < 8; ni++) {
            oacc[ni][0] *= c0; oacc[ni][1] *= c0;
            oacc[ni][2] *= c1; oacc[ni][3] *= c1;
        }

        __syncthreads();  // all warps done reading sKP (K) before P overwrite
        // write P (tf32) into sKP as [64 rows][32 cols], stride 36
#pragma unroll
        for (int ni = 0; ni < 4; ni++) {
            int col = ni * 8 + 2 * tq;
            sKP[(wm + grp) * 36 + col] = f2tf(sv[ni][0]);
            sKP[(wm + grp) * 36 + col + 1] = f2tf(sv[ni][1]);
            sKP[(wm + grp + 8) * 36 + col] = f2tf(sv[ni][2]);
            sKP[(wm + grp + 8) * 36 + col + 1] = f2tf(sv[ni][3]);
        }
        __syncwarp();

        // O += P . V   (warp reads only its own 16 P rows)
#pragma unroll
        for (int ks = 0; ks < 4; ks++) {
            int k = ks * 8 + tq;
            unsigned a[4];
            a[0] = sKP[(wm + grp) * 36 + k];
            a[1] = sKP[(wm + grp + 8) * 36 + k];
            a[2] = sKP[(wm + grp) * 36 + k + 4];
            a[3] = sKP[(wm + grp + 8) * 36 + k + 4];
#pragma unroll
            for (int ni = 0; ni < 8; ni++) {
                unsigned bfr[2];
                bfr[0] = sV[(ks * 8 + tq) * 72 + ni * 8 + grp];
                bfr[1] = sV[(ks * 8 + tq + 4) * 72 + ni * 8 + grp];
                mma8(oacc[ni], a, bfr);
            }
        }
    }

    // epilogue: normalize and store attn_vec[(i*8+b)*1024 + h*64 + d]
    float inv0 = 1.f / l0, inv1 = 1.f / l1;
#pragma unroll
    for (int ni = 0; ni < 8; ni++) {
        int d = ni * 8 + 2 * tq;
        float2 o0 = {oacc[ni][0] * inv0, oacc[ni][1] * inv0};
        float2 o1 = {oacc[ni][2] * inv1, oacc[ni][3] * inv1};
        *(float2*)(out + ((size_t)r0g * 8 + b) * 1024 + h * 64 + d) = o0;
        *(float2*)(out + ((size_t)r1g * 8 + b) * 1024 + h * 64 + d) = o1;
    }
}

// ---------------- residual + layernorm: out = LN(x + y) * g + b --------------
__global__ __launch_bounds__(256) void resid_ln_kernel(
    const float* __restrict__ x, const float* __restrict__ y,
    const float* __restrict__ g, const float* __restrict__ bta,
    float* __restrict__ out) {
    __shared__ float red[256];
    int row = blockIdx.x, t = threadIdx.x;
    const float* xr = x + (size_t)row * 1024;
    const float* yr = y + (size_t)row * 1024;
    float v[4];
    float s = 0.f;
#pragma unroll
    for (int e = 0; e < 4; e++) {
        int c = t + 256 * e;
        v[e] = xr[c] + yr[c];
        s += v[e];
    }
    red[t] = s;
    __syncthreads();
    for (int w = 128; w > 0; w >>= 1) {
        if (t < w) red[t] += red[t + w];
        __syncthreads();
    }
    float mean = red[0] * (1.f / 1024.f);
    __syncthreads();
    float s2 = 0.f;
#pragma unroll
    for (int e = 0; e < 4; e++) {
        float d = v[e] - mean;
        s2 += d * d;
    }
    red[t] = s2;
    __syncthreads();
    for (int w = 128; w > 0; w >>= 1) {
        if (t < w) red[t] += red[t + w];
        __syncthreads();
    }
    float inv = rsqrtf(red[0] * (1.f / 1024.f) + 1e-5f);
#pragma unroll
    for (int e = 0; e < 4; e++) {
        int c = t + 256 * e;
        out[(size_t)row * 1024 + c] = (v[e] - mean) * inv * g[c] + bta[c];
    }
}

// ---------------- host orchestration ----------------
extern "C" void kernel_launch(void* const* d_in, const int* in_sizes, int n_in,
                              void* d_out, int out_size) {
    const int* inp = (const int*)d_in[0];
    const float* mems = (const float*)d_in[1];
    const float* emb_table = (const float*)d_in[2];
    const float* r_w_bias = (const float*)d_in[3];
    const float* r_r_bias = (const float*)d_in[4];
    const float* qkv_w = (const float*)d_in[5];
    const float* r_w = (const float*)d_in[6];
    const float* o_w = (const float*)d_in[7];
    const float* ln1_g = (const float*)d_in[8];
    const float* ln1_b = (const float*)d_in[9];
    const float* ff_w1 = (const float*)d_in[10];
    const float* ff_b1 = (const float*)d_in[11];
    const float* ff_w2 = (const float*)d_in[12];
    const float* ff_b2 = (const float*)d_in[13];
    const float* ln2_g = (const float*)d_in[14];
    const float* ln2_b = (const float*)d_in[15];

    void* p;
    cudaGetSymbolAddress(&p, g_core);    float* corep = (float*)p;
    cudaGetSymbolAddress(&p, g_cat);     float* catp = (float*)p;
    cudaGetSymbolAddress(&p, g_heads);   float* headsp = (float*)p;
    cudaGetSymbolAddress(&p, g_posemb);  float* posembp = (float*)p;
    cudaGetSymbolAddress(&p, g_rk);      float* rkp = (float*)p;
    cudaGetSymbolAddress(&p, g_BDr);     float* bdrp = (float*)p;
    cudaGetSymbolAddress(&p, g_attnvec); float* avecp = (float*)p;
    cudaGetSymbolAddress(&p, g_attnout); float* aoutp = (float*)p;
    cudaGetSymbolAddress(&p, g_h1);      float* h1p = (float*)p;
    cudaGetSymbolAddress(&p, g_ff);      float* ffp = (float*)p;

    const size_t CORE_BYTES = (size_t)QLEN * BSZ * DMODEL * sizeof(float);

    embed_kernel<<<QLEN * BSZ, 256>>>(inp, emb_table, corep);
    posemb_kernel<<<KLEN, 512>>>(posembp);

    for (int l = 0; l < 4; l++) {
        cudaMemcpyAsync(catp, mems + (size_t)l * MLEN * BSZ * DMODEL, CORE_BYTES,
                        cudaMemcpyDeviceToDevice);
        cudaMemcpyAsync(catp + (size_t)MLEN * BSZ * DMODEL, corep, CORE_BYTES,
                        cudaMemcpyDeviceToDevice);
        // heads = cat @ qkv_w[l]^T   (8192 x 3072 x 1024)
        gemm_nt_tf32<false, false><<<dim3(24, 64), 256>>>(
            catp, qkv_w + (size_t)l * 3 * DMODEL * DMODEL, nullptr, headsp,
            KLEN * BSZ, 3 * DMODEL, DMODEL);
        // rk = pos_emb @ r_w[l]^T    (1024 x 1024 x 1024)
        gemm_nt_tf32<false, false><<<dim3(8, 8), 256>>>(
            posembp, r_w + (size_t)l * DMODEL * DMODEL, nullptr, rkp,
            KLEN, DMODEL, DMODEL);
        // BDr = (q + r_r_bias) . rk
        qk_tf32<<<dim3(16, 8, 128), 256>>>(
            headsp + (size_t)MLEN * BSZ * 3 * DMODEL, rkp, r_r_bias, bdrp,
            0, DMODEL);
        // fused flash attention: AC + shifted BD + softmax + PV
        flash_attn<<<dim3(8, 128), 128>>>(
            headsp + (size_t)MLEN * BSZ * 3 * DMODEL, headsp + DMODEL,
            headsp + 2 * DMODEL, bdrp, r_w_bias, avecp);
        // attn_out = attn_vec @ o_w[l]^T   (4096 x 1024 x 1024)
        gemm_nt_tf32<false, false><<<dim3(8, 32), 256>>>(
            avecp, o_w + (size_t)l * DMODEL * DMODEL, nullptr, aoutp,
            QLEN * BSZ, DMODEL, DMODEL);
        resid_ln_kernel<<<QLEN * BSZ, 256>>>(corep, aoutp, ln1_g + l * DMODEL,
                                             ln1_b + l * DMODEL, corep);
        // h1 = relu(core @ ff_w1^T + b1)   (4096 x 4096 x 1024)
        gemm_nt_tf32<true, true><<<dim3(32, 32), 256>>>(
            corep, ff_w1 + (size_t)l * DINNER * DMODEL, ff_b1 + l * DINNER,
            h1p, QLEN * BSZ, DINNER, DMODEL);
        // ff = h1 @ ff_w2^T + b2           (4096 x 1024 x 4096)
        gemm_nt_tf32<false, true><<<dim3(8, 32), 256>>>(
            h1p, ff_w2 + (size_t)l * DMODEL * DINNER, ff_b2 + l * DMODEL,
            ffp, QLEN * BSZ, DMODEL, DINNER);
        resid_ln_kernel<<<QLEN * BSZ, 256>>>(corep, ffp, ln2_g + l * DMODEL,
                                             ln2_b + l * DMODEL, corep);
    }

    cudaMemcpyAsync(d_out, corep, CORE_BYTES, cudaMemcpyDeviceToDevice);
}

// round 6
// speedup vs baseline: 3.5381x; 1.3923x over previous
#include <cuda_runtime.h>
#include <cuda_fp16.h>

#define QLEN 512
#define MLEN 512
#define KLEN 1024
#define BSZ 8
#define DMODEL 1024
#define NHEAD 16
#define DHEAD 64
#define DINNER 4096

// ---------------- scratch (no allocations allowed) ----------------
__device__ float g_core[QLEN * BSZ * DMODEL];
__device__ float g_cat[KLEN * BSZ * DMODEL];
__device__ float g_heads[KLEN * BSZ * 3 * DMODEL];
__device__ float g_posemb[KLEN * DMODEL];
__device__ float g_rk[KLEN * DMODEL];
__device__ float g_BDr[BSZ * NHEAD * QLEN * KLEN];
__device__ float g_attnvec[QLEN * BSZ * DMODEL];
__device__ float g_attnout[QLEN * BSZ * DMODEL];
__device__ float g_h1[QLEN * BSZ * DINNER];
__device__ float g_ff[QLEN * BSZ * DMODEL];

// ---------------- tf32 helpers (qk / flash) ----------------
__device__ __forceinline__ unsigned f2tf(float x) {
    unsigned r;
    asm("cvt.rna.tf32.f32 %0, %1;" : "=r"(r) : "f"(x));
    return r;
}

__device__ __forceinline__ void mma8(float* c, const unsigned* a, const unsigned* b) {
    asm volatile(
        "mma.sync.aligned.m16n8k8.row.col.f32.tf32.tf32.f32 "
        "{%0,%1,%2,%3}, {%4,%5,%6,%7}, {%8,%9}, {%0,%1,%2,%3};"
        : "+f"(c[0]), "+f"(c[1]), "+f"(c[2]), "+f"(c[3])
        : "r"(a[0]), "r"(a[1]), "r"(a[2]), "r"(a[3]), "r"(b[0]), "r"(b[1]));
}

// ---------------- fp16 helpers (dense GEMM) ----------------
__device__ __forceinline__ unsigned f2h2(float a, float b) {
    __half2 h = __floats2half2_rn(a, b);
    return *(unsigned*)&h;
}

__device__ __forceinline__ void mma16(float* c, const unsigned* a,
                                      unsigned b0, unsigned b1) {
    asm volatile(
        "mma.sync.aligned.m16n8k16.row.col.f32.f16.f16.f32 "
        "{%0,%1,%2,%3}, {%4,%5,%6,%7}, {%8,%9}, {%0,%1,%2,%3};"
        : "+f"(c[0]), "+f"(c[1]), "+f"(c[2]), "+f"(c[3])
        : "r"(a[0]), "r"(a[1]), "r"(a[2]), "r"(a[3]), "r"(b0), "r"(b1));
}

__device__ __forceinline__ void ldsm4(unsigned* r, const __half* p) {
    unsigned addr = (unsigned)__cvta_generic_to_shared(p);
    asm volatile("ldmatrix.sync.aligned.m8n8.x4.shared.b16 {%0,%1,%2,%3}, [%4];"
                 : "=r"(r[0]), "=r"(r[1]), "=r"(r[2]), "=r"(r[3])
                 : "r"(addr));
}

// ---------------- embedding lookup: core = emb[inp] * sqrt(D) ----------------
__global__ void embed_kernel(const int* __restrict__ inp,
                             const float* __restrict__ emb,
                             float* __restrict__ core) {
    int row = blockIdx.x;
    int tok = inp[row];
    const float4* src = (const float4*)(emb + (size_t)tok * DMODEL);
    float4* dst = (float4*)(core + (size_t)row * DMODEL);
    float4 v = src[threadIdx.x];
    v.x *= 32.f; v.y *= 32.f; v.z *= 32.f; v.w *= 32.f;
    dst[threadIdx.x] = v;
}

// ---------------- sinusoidal positional embedding ----------------
__global__ void posemb_kernel(float* __restrict__ pe) {
    int k = blockIdx.x;
    int j = threadIdx.x;
    double invf = exp(-(2.0 * (double)j / 1024.0) * log(10000.0));
    double ang = (double)(KLEN - 1 - k) * invf;
    pe[(size_t)k * DMODEL + j] = (float)sin(ang);
    pe[(size_t)k * DMODEL + 512 + j] = (float)cos(ang);
}

// ---------------- NT GEMM via fp16 mma.sync + ldmatrix ----------------------
// C[M,N] = A[M,K] B[N,K]^T. CTA tile 128x128, k-tile 32, double-buffered.
// Smem rows: stride 40 halves (80B, mult of 16) -> ldmatrix conflict-free.
template <bool RELU, bool HASBIAS>
__global__ __launch_bounds__(256, 2) void gemm_nt_f16(
    const float* __restrict__ A, const float* __restrict__ B,
    const float* __restrict__ bias, float* __restrict__ C,
    int M, int N, int K) {
    __shared__ __align__(16) __half sA[2][128 * 40];
    __shared__ __align__(16) __half sB[2][128 * 40];
    const int t = threadIdx.x;
    const int m0 = blockIdx.y * 128, n0 = blockIdx.x * 128;
    const int lane = t & 31, wid = t >> 5;
    const int grp = lane >> 2, tq = lane & 3;
    const int wm = (wid & 1) * 64, wn = (wid >> 1) * 32;
    const int l15 = lane & 15, lhi = (lane >> 4) * 8;
    const float* Ab = A + (size_t)m0 * K;
    const float* Bb = B + (size_t)n0 * K;

    int fr[4], fc[4];
#pragma unroll
    for (int i = 0; i < 4; i++) {
        int idx = t + 256 * i;
        fr[i] = idx >> 3;          // 0..127
        fc[i] = (idx & 7) << 2;    // 0,4,..,28
    }

    float acc[4][4][4] = {};
    float4 pa[4], pb[4];

#pragma unroll
    for (int i = 0; i < 4; i++) {
        pa[i] = *(const float4*)(Ab + (size_t)fr[i] * K + fc[i]);
        pb[i] = *(const float4*)(Bb + (size_t)fr[i] * K + fc[i]);
    }

    int s = 0;
    for (int k0 = 0; k0 < K; k0 += 32) {
#pragma unroll
        for (int i = 0; i < 4; i++) {
            *(uint2*)&sA[s][fr[i] * 40 + fc[i]] =
                make_uint2(f2h2(pa[i].x, pa[i].y), f2h2(pa[i].z, pa[i].w));
            *(uint2*)&sB[s][fr[i] * 40 + fc[i]] =
                make_uint2(f2h2(pb[i].x, pb[i].y), f2h2(pb[i].z, pb[i].w));
        }
        __syncthreads();
        if (k0 + 32 < K) {
#pragma unroll
            for (int i = 0; i < 4; i++) {
                pa[i] = *(const float4*)(Ab + (size_t)fr[i] * K + k0 + 32 + fc[i]);
                pb[i] = *(const float4*)(Bb + (size_t)fr[i] * K + k0 + 32 + fc[i]);
            }
        }
        const __half* as = sA[s];
        const __half* bs = sB[s];
#pragma unroll
        for (int ks = 0; ks < 2; ks++) {
            unsigned af[4][4], bf[2][4];
#pragma unroll
            for (int mi = 0; mi < 4; mi++)
                ldsm4(af[mi], &as[(wm + mi * 16 + l15) * 40 + ks * 16 + lhi]);
#pragma unroll
            for (int nc = 0; nc < 2; nc++)
                ldsm4(bf[nc], &bs[(wn + nc * 16 + l15) * 40 + ks * 16 + lhi]);
#pragma unroll
            for (int mi = 0; mi < 4; mi++)
#pragma unroll
                for (int ni = 0; ni < 4; ni++) {
                    int nc = ni >> 1, w = ni & 1;
                    mma16(acc[mi][ni], af[mi], bf[nc][w], bf[nc][w + 2]);
                }
        }
        s ^= 1;
    }

#pragma unroll
    for (int mi = 0; mi < 4; mi++)
#pragma unroll
        for (int ni = 0; ni < 4; ni++) {
            int col = n0 + wn + ni * 8 + 2 * tq;
            float b0 = 0.f, b1 = 0.f;
            if (HASBIAS) { b0 = __ldg(bias + col); b1 = __ldg(bias + col + 1); }
#pragma unroll
            for (int hh = 0; hh < 2; hh++) {
                int row = m0 + wm + mi * 16 + grp + hh * 8;
                float2 o;
                o.x = acc[mi][ni][hh * 2 + 0] + b0;
                o.y = acc[mi][ni][hh * 2 + 1] + b1;
                if (RELU) { o.x = fmaxf(o.x, 0.f); o.y = fmaxf(o.y, 0.f); }
                *(float2*)(C + (size_t)row * N + col) = o;
            }
        }
}

// ---------------- batched (q+bias)·B^T via tf32 mma, 64x64 tiles, K=64 -------
// Used only for BDr = (q + r_r_bias) · rk
__global__ __launch_bounds__(256) void qk_tf32(
    const float* __restrict__ qbase, const float* __restrict__ bbase,
    const float* __restrict__ bias, float* __restrict__ out,
    int b_batch_stride, int b_row_stride) {
    __shared__ unsigned Qs[64][68];
    __shared__ unsigned Ks[64][68];
    int bh = blockIdx.z;
    int b = bh >> 4, h = bh & 15;
    int i0 = blockIdx.y * 64, j0 = blockIdx.x * 64;
    int t = threadIdx.x;
    const float* qp = qbase + b * 3072 + h * 64;
    const float* kp = bbase + b * b_batch_stride + h * 64;
    const float* bi = bias + h * 64;

#pragma unroll
    for (int i = 0; i < 4; i++) {
        int idx = t + 256 * i;
        int r = idx >> 4;
        int c = (idx & 15) << 2;
        float4 qv = *(const float4*)(qp + (size_t)(i0 + r) * 24576 + c);
        float4 bb = *(const float4*)(bi + c);
        *(uint4*)&Qs[r][c] = make_uint4(f2tf(qv.x + bb.x), f2tf(qv.y + bb.y),
                                        f2tf(qv.z + bb.z), f2tf(qv.w + bb.w));
        float4 kv = *(const float4*)(kp + (size_t)(j0 + r) * b_row_stride + c);
        *(uint4*)&Ks[r][c] = make_uint4(f2tf(kv.x), f2tf(kv.y), f2tf(kv.z), f2tf(kv.w));
    }
    __syncthreads();

    int lane = t & 31, wid = t >> 5;
    int grp = lane >> 2, tq = lane & 3;
    int wm = (wid & 1) * 32, wn = (wid >> 1) * 16;
    float acc[2][2][4] = {};

#pragma unroll
    for (int ks = 0; ks < 8; ks++) {
        int k = ks * 8 + tq;
        unsigned af[2][4], bf[2][2];
#pragma unroll
        for (int mi = 0; mi < 2; mi++) {
            int r = wm + mi * 16 + grp;
            af[mi][0] = Qs[r][k];
            af[mi][1] = Qs[r + 8][k];
            af[mi][2] = Qs[r][k + 4];
            af[mi][3] = Qs[r + 8][k + 4];
        }
#pragma unroll
        for (int ni = 0; ni < 2; ni++) {
            int n = wn + ni * 8 + grp;
            bf[ni][0] = Ks[n][k];
            bf[ni][1] = Ks[n][k + 4];
        }
#pragma unroll
        for (int mi = 0; mi < 2; mi++)
#pragma unroll
            for (int ni = 0; ni < 2; ni++) mma8(acc[mi][ni], af[mi], bf[ni]);
    }

#pragma unroll
    for (int mi = 0; mi < 2; mi++)
#pragma unroll
        for (int ni = 0; ni < 2; ni++)
#pragma unroll
            for (int hh = 0; hh < 2; hh++) {
                int row = i0 + wm + mi * 16 + grp + hh * 8;
                int col = j0 + wn + ni * 8 + 2 * tq;
                float2 o = {acc[mi][ni][hh * 2], acc[mi][ni][hh * 2 + 1]};
                *(float2*)(out + ((size_t)bh * 512 + row) * 1024 + col) = o;
            }
}

// ---------------- flash attention: AC + BDr-gather + online softmax + PV -----
__global__ __launch_bounds__(128) void flash_attn(
    const float* __restrict__ qbase, const float* __restrict__ kbase,
    const float* __restrict__ vbase, const float* __restrict__ BDr,
    const float* __restrict__ rwb, float* __restrict__ out) {
    __shared__ unsigned sQ[64 * 68];
    __shared__ unsigned sKP[64 * 36];
    __shared__ unsigned sV[32 * 72];

    const int i0 = blockIdx.x * 64;
    const int bh = blockIdx.y;
    const int b = bh >> 4, h = bh & 15;
    const int t = threadIdx.x;
    const int lane = t & 31;
    const int wid = t >> 5;
    const int grp = lane >> 2, tq = lane & 3;
    const int wm = wid * 16;

    const float* qp = qbase + b * 3072 + h * 64;
    const float* kp = kbase + b * 3072 + h * 64;
    const float* vp = vbase + b * 3072 + h * 64;
    const float* bdp = BDr + (size_t)bh * QLEN * KLEN;

#pragma unroll
    for (int i = 0; i < 8; i++) {
        int f = t + 128 * i;
        int r = f >> 4;
        int c = (f & 15) << 2;
        float4 qv = *(const float4*)(qp + (size_t)(i0 + r) * 24576 + c);
        float4 bb = *(const float4*)(rwb + h * 64 + c);
        sQ[r * 68 + c + 0] = f2tf(qv.x + bb.x);
        sQ[r * 68 + c + 1] = f2tf(qv.y + bb.y);
        sQ[r * 68 + c + 2] = f2tf(qv.z + bb.z);
        sQ[r * 68 + c + 3] = f2tf(qv.w + bb.w);
    }

    const int r0g = i0 + wm + grp;
    const int r1g = r0g + 8;
    float m0 = -3e38f, m1 = -3e38f, l0 = 0.f, l1 = 0.f;
    float oacc[8][4] = {};

    const int njt = (i0 + 576) >> 5;
    for (int jt = 0; jt < njt; jt++) {
        const int j0 = jt * 32;
        __syncthreads();
#pragma unroll
        for (int i = 0; i < 4; i++) {
            int f = t + 128 * i;
            int r = f >> 4;
            int c = (f & 15) << 2;
            float4 kv = *(const float4*)(kp + (size_t)(j0 + r) * 24576 + c);
            sKP[r * 68 + c + 0] = f2tf(kv.x);
            sKP[r * 68 + c + 1] = f2tf(kv.y);
            sKP[r * 68 + c + 2] = f2tf(kv.z);
            sKP[r * 68 + c + 3] = f2tf(kv.w);
            float4 vv = *(const float4*)(vp + (size_t)(j0 + r) * 24576 + c);
            sV[r * 72 + c + 0] = f2tf(vv.x);
            sV[r * 72 + c + 1] = f2tf(vv.y);
            sV[r * 72 + c + 2] = f2tf(vv.z);
            sV[r * 72 + c + 3] = f2tf(vv.w);
        }
        __syncthreads();

        float sacc[4][4] = {};
#pragma unroll
        for (int ks = 0; ks < 8; ks++) {
            int k = ks * 8 + tq;
            unsigned a[4];
            a[0] = sQ[(wm + grp) * 68 + k];
            a[1] = sQ[(wm + grp + 8) * 68 + k];
            a[2] = sQ[(wm + grp) * 68 + k + 4];
            a[3] = sQ[(wm + grp + 8) * 68 + k + 4];
#pragma unroll
            for (int ni = 0; ni < 4; ni++) {
                unsigned bfr[2];
                bfr[0] = sKP[(ni * 8 + grp) * 68 + k];
                bfr[1] = sKP[(ni * 8 + grp) * 68 + k + 4];
                mma8(sacc[ni], a, bfr);
            }
        }

        float sv[4][4];
#pragma unroll
        for (int ni = 0; ni < 4; ni++)
#pragma unroll
            for (int v = 0; v < 4; v++) {
                int jg = j0 + ni * 8 + 2 * tq + (v & 1);
                int ig = (v < 2) ? r0g : r1g;
                float x = -3e38f;
                if (jg <= ig + 512) {
                    float bd = __ldg(bdp + (size_t)ig * KLEN + (jg + 511 - ig));
                    x = (sacc[ni][v] + bd) * 0.125f;
                }
                sv[ni][v] = x;
            }

        float rm0 = -3e38f, rm1 = -3e38f;
#pragma unroll
        for (int ni = 0; ni < 4; ni++) {
            rm0 = fmaxf(rm0, fmaxf(sv[ni][0], sv[ni][1]));
            rm1 = fmaxf(rm1, fmaxf(sv[ni][2], sv[ni][3]));
        }
        rm0 = fmaxf(rm0, __shfl_xor_sync(0xffffffff, rm0, 1));
        rm0 = fmaxf(rm0, __shfl_xor_sync(0xffffffff, rm0, 2));
        rm1 = fmaxf(rm1, __shfl_xor_sync(0xffffffff, rm1, 1));
        rm1 = fmaxf(rm1, __shfl_xor_sync(0xffffffff, rm1, 2));
        float mn0 = fmaxf(m0, rm0), mn1 = fmaxf(m1, rm1);
        float c0 = exp2f((m0 - mn0) * 1.44269504f);
        float c1 = exp2f((m1 - mn1) * 1.44269504f);
        float rs0 = 0.f, rs1 = 0.f;
#pragma unroll
        for (int ni = 0; ni < 4; ni++) {
            sv[ni][0] = exp2f((sv[ni][0] - mn0) * 1.44269504f);
            sv[ni][1] = exp2f((sv[ni][1] - mn0) * 1.44269504f);
            sv[ni][2] = exp2f((sv[ni][2] - mn1) * 1.44269504f);
            sv[ni][3] = exp2f((sv[ni][3] - mn1) * 1.44269504f);
            rs0 += sv[ni][0] + sv[ni][1];
            rs1 += sv[ni][2] + sv[ni][3];
        }
        rs0 += __shfl_xor_sync(0xffffffff, rs0, 1);
        rs0 += __shfl_xor_sync(0xffffffff, rs0, 2);
        rs1 += __shfl_xor_sync(0xffffffff, rs1, 1);
        rs1 += __shfl_xor_sync(0xffffffff, rs1, 2);
        l0 = l0 * c0 + rs0;
        l1 = l1 * c1 + rs1;
        m0 = mn0; m1 = mn1;
#pragma unroll
        for (int ni = 0; ni < 8; ni++) {
            oacc[ni][0] *= c0; oacc[ni][1] *= c0;
            oacc[ni][2] *= c1; oacc[ni][3] *= c1;
        }

        __syncthreads();
#pragma unroll
        for (int ni = 0; ni < 4; ni++) {
            int col = ni * 8 + 2 * tq;
            sKP[(wm + grp) * 36 + col] = f2tf(sv[ni][0]);
            sKP[(wm + grp) * 36 + col + 1] = f2tf(sv[ni][1]);
            sKP[(wm + grp + 8) * 36 + col] = f2tf(sv[ni][2]);
            sKP[(wm + grp + 8) * 36 + col + 1] = f2tf(sv[ni][3]);
        }
        __syncwarp();

#pragma unroll
        for (int ks = 0; ks < 4; ks++) {
            int k = ks * 8 + tq;
            unsigned a[4];
            a[0] = sKP[(wm + grp) * 36 + k];
            a[1] = sKP[(wm + grp + 8) * 36 + k];
            a[2] = sKP[(wm + grp) * 36 + k + 4];
            a[3] = sKP[(wm + grp + 8) * 36 + k + 4];
#pragma unroll
            for (int ni = 0; ni < 8; ni++) {
                unsigned bfr[2];
                bfr[0] = sV[(ks * 8 + tq) * 72 + ni * 8 + grp];
                bfr[1] = sV[(ks * 8 + tq + 4) * 72 + ni * 8 + grp];
                mma8(oacc[ni], a, bfr);
            }
        }
    }

    float inv0 = 1.f / l0, inv1 = 1.f / l1;
#pragma unroll
    for (int ni = 0; ni < 8; ni++) {
        int d = ni * 8 + 2 * tq;
        float2 o0 = {oacc[ni][0] * inv0, oacc[ni][1] * inv0};
        float2 o1 = {oacc[ni][2] * inv1, oacc[ni][3] * inv1};
        *(float2*)(out + ((size_t)r0g * 8 + b) * 1024 + h * 64 + d) = o0;
        *(float2*)(out + ((size_t)r1g * 8 + b) * 1024 + h * 64 + d) = o1;
    }
}

// ---------------- residual + layernorm: out = LN(x + y) * g + b --------------
__global__ __launch_bounds__(256) void resid_ln_kernel(
    const float* __restrict__ x, const float* __restrict__ y,
    const float* __restrict__ g, const float* __restrict__ bta,
    float* __restrict__ out) {
    __shared__ float red[256];
    int row = blockIdx.x, t = threadIdx.x;
    const float* xr = x + (size_t)row * 1024;
    const float* yr = y + (size_t)row * 1024;
    float v[4];
    float s = 0.f;
#pragma unroll
    for (int e = 0; e < 4; e++) {
        int c = t + 256 * e;
        v[e] = xr[c] + yr[c];
        s += v[e];
    }
    red[t] = s;
    __syncthreads();
    for (int w = 128; w > 0; w >>= 1) {
        if (t < w) red[t] += red[t + w];
        __syncthreads();
    }
    float mean = red[0] * (1.f / 1024.f);
    __syncthreads();
    float s2 = 0.f;
#pragma unroll
    for (int e = 0; e < 4; e++) {
        float d = v[e] - mean;
        s2 += d * d;
    }
    red[t] = s2;
    __syncthreads();
    for (int w = 128; w > 0; w >>= 1) {
        if (t < w) red[t] += red[t + w];
        __syncthreads();
    }
    float inv = rsqrtf(red[0] * (1.f / 1024.f) + 1e-5f);
#pragma unroll
    for (int e = 0; e < 4; e++) {
        int c = t + 256 * e;
        out[(size_t)row * 1024 + c] = (v[e] - mean) * inv * g[c] + bta[c];
    }
}

// ---------------- host orchestration ----------------
extern "C" void kernel_launch(void* const* d_in, const int* in_sizes, int n_in,
                              void* d_out, int out_size) {
    const int* inp = (const int*)d_in[0];
    const float* mems = (const float*)d_in[1];
    const float* emb_table = (const float*)d_in[2];
    const float* r_w_bias = (const float*)d_in[3];
    const float* r_r_bias = (const float*)d_in[4];
    const float* qkv_w = (const float*)d_in[5];
    const float* r_w = (const float*)d_in[6];
    const float* o_w = (const float*)d_in[7];
    const float* ln1_g = (const float*)d_in[8];
    const float* ln1_b = (const float*)d_in[9];
    const float* ff_w1 = (const float*)d_in[10];
    const float* ff_b1 = (const float*)d_in[11];
    const float* ff_w2 = (const float*)d_in[12];
    const float* ff_b2 = (const float*)d_in[13];
    const float* ln2_g = (const float*)d_in[14];
    const float* ln2_b = (const float*)d_in[15];

    void* p;
    cudaGetSymbolAddress(&p, g_core);    float* corep = (float*)p;
    cudaGetSymbolAddress(&p, g_cat);     float* catp = (float*)p;
    cudaGetSymbolAddress(&p, g_heads);   float* headsp = (float*)p;
    cudaGetSymbolAddress(&p, g_posemb);  float* posembp = (float*)p;
    cudaGetSymbolAddress(&p, g_rk);      float* rkp = (float*)p;
    cudaGetSymbolAddress(&p, g_BDr);     float* bdrp = (float*)p;
    cudaGetSymbolAddress(&p, g_attnvec); float* avecp = (float*)p;
    cudaGetSymbolAddress(&p, g_attnout); float* aoutp = (float*)p;
    cudaGetSymbolAddress(&p, g_h1);      float* h1p = (float*)p;
    cudaGetSymbolAddress(&p, g_ff);      float* ffp = (float*)p;

    const size_t CORE_BYTES = (size_t)QLEN * BSZ * DMODEL * sizeof(float);

    embed_kernel<<<QLEN * BSZ, 256>>>(inp, emb_table, corep);
    posemb_kernel<<<KLEN, 512>>>(posembp);

    for (int l = 0; l < 4; l++) {
        cudaMemcpyAsync(catp, mems + (size_t)l * MLEN * BSZ * DMODEL, CORE_BYTES,
                        cudaMemcpyDeviceToDevice);
        cudaMemcpyAsync(catp + (size_t)MLEN * BSZ * DMODEL, corep, CORE_BYTES,
                        cudaMemcpyDeviceToDevice);
        // heads = cat @ qkv_w[l]^T   (8192 x 3072 x 1024)
        gemm_nt_f16<false, false><<<dim3(24, 64), 256>>>(
            catp, qkv_w + (size_t)l * 3 * DMODEL * DMODEL, nullptr, headsp,
            KLEN * BSZ, 3 * DMODEL, DMODEL);
        // rk = pos_emb @ r_w[l]^T    (1024 x 1024 x 1024)
        gemm_nt_f16<false, false><<<dim3(8, 8), 256>>>(
            posembp, r_w + (size_t)l * DMODEL * DMODEL, nullptr, rkp,
            KLEN, DMODEL, DMODEL);
        // BDr = (q + r_r_bias) . rk
        qk_tf32<<<dim3(16, 8, 128), 256>>>(
            headsp + (size_t)MLEN * BSZ * 3 * DMODEL, rkp, r_r_bias, bdrp,
            0, DMODEL);
        // fused flash attention: AC + shifted BD + softmax + PV
        flash_attn<<<dim3(8, 128), 128>>>(
            headsp + (size_t)MLEN * BSZ * 3 * DMODEL, headsp + DMODEL,
            headsp + 2 * DMODEL, bdrp, r_w_bias, avecp);
        // attn_out = attn_vec @ o_w[l]^T   (4096 x 1024 x 1024)
        gemm_nt_f16<false, false><<<dim3(8, 32), 256>>>(
            avecp, o_w + (size_t)l * DMODEL * DMODEL, nullptr, aoutp,
            QLEN * BSZ, DMODEL, DMODEL);
        resid_ln_kernel<<<QLEN * BSZ, 256>>>(corep, aoutp, ln1_g + l * DMODEL,
                                             ln1_b + l * DMODEL, corep);
        // h1 = relu(core @ ff_w1^T + b1)   (4096 x 4096 x 1024)
        gemm_nt_f16<true, true><<<dim3(32, 32), 256>>>(
            corep, ff_w1 + (size_t)l * DINNER * DMODEL, ff_b1 + l * DINNER,
            h1p, QLEN * BSZ, DINNER, DMODEL);
        // ff = h1 @ ff_w2^T + b2           (4096 x 1024 x 4096)
        gemm_nt_f16<false, true><<<dim3(8, 32), 256>>>(
            h1p, ff_w2 + (size_t)l * DMODEL * DINNER, ff_b2 + l * DMODEL,
            ffp, QLEN * BSZ, DMODEL, DINNER);
        resid_ln_kernel<<<QLEN * BSZ, 256>>>(corep, ffp, ln2_g + l * DMODEL,
                                             ln2_b + l * DMODEL, corep);
    }

    cudaMemcpyAsync(d_out, corep, CORE_BYTES, cudaMemcpyDeviceToDevice);
}

// round 10
// speedup vs baseline: 3.9721x; 1.1227x over previous
#include <cuda_runtime.h>
#include <cuda_fp16.h>

#define QLEN 512
#define MLEN 512
#define KLEN 1024
#define BSZ 8
#define DMODEL 1024
#define NHEAD 16
#define DHEAD 64
#define DINNER 4096

// ---------------- scratch (no allocations allowed) ----------------
__device__ float g_core[QLEN * BSZ * DMODEL];
__device__ float g_heads[KLEN * BSZ * 3 * DMODEL];
__device__ float g_BDr[BSZ * NHEAD * QLEN * KLEN];
__device__ float g_attnout[QLEN * BSZ * DMODEL];
__device__ float g_ff[QLEN * BSZ * DMODEL];

__device__ __half g_cath[KLEN * BSZ * DMODEL];
__device__ __half g_pemh[KLEN * DMODEL];
__device__ __half g_rkh[KLEN * DMODEL];
__device__ __half g_coreh[QLEN * BSZ * DMODEL];
__device__ __half g_avech[QLEN * BSZ * DMODEL];
__device__ __half g_h1h[QLEN * BSZ * DINNER];

__device__ __half g_qkvwh[4 * 3 * DMODEL * DMODEL];
__device__ __half g_rwh[4 * DMODEL * DMODEL];
__device__ __half g_owh[4 * DMODEL * DMODEL];
__device__ __half g_w1h[4 * DINNER * DMODEL];
__device__ __half g_w2h[4 * DMODEL * DINNER];

// ---------------- helpers ----------------
__device__ __forceinline__ unsigned f2tf(float x) {
    unsigned r;
    asm("cvt.rna.tf32.f32 %0, %1;" : "=r"(r) : "f"(x));
    return r;
}

__device__ __forceinline__ void mma8(float* c, const unsigned* a, const unsigned* b) {
    asm volatile(
        "mma.sync.aligned.m16n8k8.row.col.f32.tf32.tf32.f32 "
        "{%0,%1,%2,%3}, {%4,%5,%6,%7}, {%8,%9}, {%0,%1,%2,%3};"
        : "+f"(c[0]), "+f"(c[1]), "+f"(c[2]), "+f"(c[3])
        : "r"(a[0]), "r"(a[1]), "r"(a[2]), "r"(a[3]), "r"(b[0]), "r"(b[1]));
}

__device__ __forceinline__ unsigned f2h2(float a, float b) {
    __half2 h = __floats2half2_rn(a, b);
    return *(unsigned*)&h;
}

__device__ __forceinline__ void mma16(float* c, const unsigned* a,
                                      unsigned b0, unsigned b1) {
    asm volatile(
        "mma.sync.aligned.m16n8k16.row.col.f32.f16.f16.f32 "
        "{%0,%1,%2,%3}, {%4,%5,%6,%7}, {%8,%9}, {%0,%1,%2,%3};"
        : "+f"(c[0]), "+f"(c[1]), "+f"(c[2]), "+f"(c[3])
        : "r"(a[0]), "r"(a[1]), "r"(a[2]), "r"(a[3]), "r"(b0), "r"(b1));
}

__device__ __forceinline__ void ldsm4(unsigned* r, const __half* p) {
    unsigned addr = (unsigned)__cvta_generic_to_shared(p);
    asm volatile("ldmatrix.sync.aligned.m8n8.x4.shared.b16 {%0,%1,%2,%3}, [%4];"
                 : "=r"(r[0]), "=r"(r[1]), "=r"(r[2]), "=r"(r[3])
                 : "r"(addr));
}

// ---------------- weight fp32 -> fp16 ----------------
__global__ void w2h_kernel(const float* __restrict__ src, __half* __restrict__ dst,
                           int n4) {
    int i = blockIdx.x * 256 + threadIdx.x;
    if (i < n4) {
        float4 v = ((const float4*)src)[i];
        uint2 o = make_uint2(f2h2(v.x, v.y), f2h2(v.z, v.w));
        *(uint2*)(dst + (size_t)i * 4) = o;
    }
}

// ---------------- embedding lookup: core = emb[inp] * sqrt(D) ----------------
__global__ void embed_kernel(const int* __restrict__ inp,
                             const float* __restrict__ emb,
                             float* __restrict__ core) {
    int row = blockIdx.x;
    int tok = inp[row];
    const float4* src = (const float4*)(emb + (size_t)tok * DMODEL);
    float4* dst = (float4*)(core + (size_t)row * DMODEL);
    float4 v = src[threadIdx.x];
    v.x *= 32.f; v.y *= 32.f; v.z *= 32.f; v.w *= 32.f;
    dst[threadIdx.x] = v;
}

// ---------------- cat (fp16) = [mems_l ; core] ----------------
__global__ void cat_f16_kernel(const float* __restrict__ mems_l,
                               const float* __restrict__ core,
                               __half* __restrict__ cath) {
    int row = blockIdx.x;
    int t = threadIdx.x;
    const float* s = (row < MLEN * BSZ) ? mems_l + (size_t)row * DMODEL
                                        : core + (size_t)(row - MLEN * BSZ) * DMODEL;
    float4 v = ((const float4*)s)[t];
    uint2 o = make_uint2(f2h2(v.x, v.y), f2h2(v.z, v.w));
    *(uint2*)(cath + (size_t)row * DMODEL + t * 4) = o;
}

// ---------------- sinusoidal positional embedding (fp16) ----------------
__global__ void posemb_kernel(__half* __restrict__ pe) {
    int k = blockIdx.x;
    int j = threadIdx.x;
    double invf = exp(-(2.0 * (double)j / 1024.0) * log(10000.0));
    double ang = (double)(KLEN - 1 - k) * invf;
    pe[(size_t)k * DMODEL + j] = __float2half((float)sin(ang));
    pe[(size_t)k * DMODEL + 512 + j] = __float2half((float)cos(ang));
}

// ---------------- NT GEMM: fp16 A/B in gmem, LDG double-buffer + ldmatrix ----
// C[M,N] = A[M,K] B[N,K]^T. CTA 128x128, k-tile 32, one barrier per k-tile.
template <bool RELU, bool HASBIAS, bool OUTF16>
__global__ __launch_bounds__(256, 2) void gemm_nt_h(
    const __half* __restrict__ A, const __half* __restrict__ B,
    const float* __restrict__ bias, float* __restrict__ C,
    __half* __restrict__ Ch, int M, int N, int K) {
    __shared__ __align__(16) __half sA[2][128 * 40];
    __shared__ __align__(16) __half sB[2][128 * 40];
    const int t = threadIdx.x;
    const int m0 = blockIdx.y * 128, n0 = blockIdx.x * 128;
    const int lane = t & 31, wid = t >> 5;
    const int grp = lane >> 2, tq = lane & 3;
    const int wm = (wid & 1) * 64, wn = (wid >> 1) * 32;
    const int l15 = lane & 15, lhi = (lane >> 4) * 8;
    const __half* Ab = A + (size_t)m0 * K;
    const __half* Bb = B + (size_t)n0 * K;

    int cr[2], cc[2];
#pragma unroll
    for (int i = 0; i < 2; i++) {
        int idx = t + 256 * i;       // 0..511
        cr[i] = idx >> 2;            // 0..127
        cc[i] = (idx & 3) * 8;       // 0,8,16,24 halfs (max 24+8=32 <= 40 OK)
    }

    float acc[4][4][4] = {};
    const int NKT = K >> 5;
    uint4 pa[2], pb[2];

#pragma unroll
    for (int i = 0; i < 2; i++) {
        pa[i] = *(const uint4*)(Ab + (size_t)cr[i] * K + cc[i]);
        pb[i] = *(const uint4*)(Bb + (size_t)cr[i] * K + cc[i]);
    }

    for (int kt = 0; kt < NKT; kt++) {
        int s = kt & 1;
#pragma unroll
        for (int i = 0; i < 2; i++) {
            *(uint4*)&sA[s][cr[i] * 40 + cc[i]] = pa[i];
            *(uint4*)&sB[s][cr[i] * 40 + cc[i]] = pb[i];
        }
        __syncthreads();
        if (kt + 1 < NKT) {
            int kn = (kt + 1) * 32;
#pragma unroll
            for (int i = 0; i < 2; i++) {
                pa[i] = *(const uint4*)(Ab + (size_t)cr[i] * K + kn + cc[i]);
                pb[i] = *(const uint4*)(Bb + (size_t)cr[i] * K + kn + cc[i]);
            }
        }
        const __half* as = sA[s];
        const __half* bs = sB[s];
#pragma unroll
        for (int ks = 0; ks < 2; ks++) {
            unsigned af[4][4], bf[2][4];
#pragma unroll
            for (int mi = 0; mi < 4; mi++)
                ldsm4(af[mi], &as[(wm + mi * 16 + l15) * 40 + ks * 16 + lhi]);
#pragma unroll
            for (int nc = 0; nc < 2; nc++)
                ldsm4(bf[nc], &bs[(wn + nc * 16 + l15) * 40 + ks * 16 + lhi]);
#pragma unroll
            for (int mi = 0; mi < 4; mi++)
#pragma unroll
                for (int ni = 0; ni < 4; ni++) {
                    int nc = ni >> 1, w = ni & 1;
                    mma16(acc[mi][ni], af[mi], bf[nc][w], bf[nc][w + 2]);
                }
        }
    }

#pragma unroll
    for (int mi = 0; mi < 4; mi++)
#pragma unroll
        for (int ni = 0; ni < 4; ni++) {
            int col = n0 + wn + ni * 8 + 2 * tq;
            float b0 = 0.f, b1 = 0.f;
            if (HASBIAS) { b0 = __ldg(bias + col); b1 = __ldg(bias + col + 1); }
#pragma unroll
            for (int hh = 0; hh < 2; hh++) {
                int row = m0 + wm + mi * 16 + grp + hh * 8;
                float ox = acc[mi][ni][hh * 2 + 0] + b0;
                float oy = acc[mi][ni][hh * 2 + 1] + b1;
                if (RELU) { ox = fmaxf(ox, 0.f); oy = fmaxf(oy, 0.f); }
                if (OUTF16) {
                    unsigned hv = f2h2(ox, oy);
                    *(unsigned*)(Ch + (size_t)row * N + col) = hv;
                } else {
                    float2 o = {ox, oy};
                    *(float2*)(C + (size_t)row * N + col) = o;
                }
            }
        }
}

// ---------------- BDr = (q + r_r_bias) . rk^T  (fp16 mma, 64x64 tiles) ------
// Row stride 72 halves (144B, odd multiple of 8 halves -> ldmatrix conflict-free,
// and >= 64 data halves so the uint4 fill stays in-bounds).
__global__ __launch_bounds__(256) void qk_f16(
    const float* __restrict__ qbase, const __half* __restrict__ rkh,
    const float* __restrict__ bias, float* __restrict__ out) {
    __shared__ __align__(16) __half Qs[64 * 72];
    __shared__ __align__(16) __half Ks[64 * 72];
    int bh = blockIdx.z;
    int b = bh >> 4, h = bh & 15;
    int i0 = blockIdx.y * 64, j0 = blockIdx.x * 64;
    int t = threadIdx.x;
    const float* qp = qbase + b * 3072 + h * 64;
    const __half* rkp = rkh + h * 64;   // per-head slice of rk (klen, H, dh)
    const float* bi = bias + h * 64;

#pragma unroll
    for (int i = 0; i < 2; i++) {
        int idx = t + 256 * i;       // 0..511
        int r = idx >> 3;            // 0..63
        int c = (idx & 7) * 8;       // 0..56  (c+8 <= 64 <= 72 stride: in-bounds)
        float4 q0 = *(const float4*)(qp + (size_t)(i0 + r) * 24576 + c);
        float4 q1 = *(const float4*)(qp + (size_t)(i0 + r) * 24576 + c + 4);
        float4 b0 = *(const float4*)(bi + c);
        float4 b1 = *(const float4*)(bi + c + 4);
        uint4 o = make_uint4(f2h2(q0.x + b0.x, q0.y + b0.y),
                             f2h2(q0.z + b0.z, q0.w + b0.w),
                             f2h2(q1.x + b1.x, q1.y + b1.y),
                             f2h2(q1.z + b1.z, q1.w + b1.w));
        *(uint4*)&Qs[r * 72 + c] = o;
        *(uint4*)&Ks[r * 72 + c] = *(const uint4*)(rkp + (size_t)(j0 + r) * DMODEL + c);
    }
    __syncthreads();

    int lane = t & 31, wid = t >> 5;
    int grp = lane >> 2, tq = lane & 3;
    int l15 = lane & 15, lhi = (lane >> 4) * 8;
    int wm = (wid & 1) * 32, wn = (wid >> 1) * 16;
    float acc[2][2][4] = {};

#pragma unroll
    for (int ks = 0; ks < 4; ks++) {
        unsigned af[2][4], bf[4];
#pragma unroll
        for (int mi = 0; mi < 2; mi++)
            ldsm4(af[mi], &Qs[(wm + mi * 16 + l15) * 72 + ks * 16 + lhi]);
        ldsm4(bf, &Ks[(wn + l15) * 72 + ks * 16 + lhi]);
#pragma unroll
        for (int mi = 0; mi < 2; mi++)
#pragma unroll
            for (int ni = 0; ni < 2; ni++)
                mma16(acc[mi][ni], af[mi], bf[ni], bf[ni + 2]);
    }

#pragma unroll
    for (int mi = 0; mi < 2; mi++)
#pragma unroll
        for (int ni = 0; ni < 2; ni++)
#pragma unroll
            for (int hh = 0; hh < 2; hh++) {
                int row = i0 + wm + mi * 16 + grp + hh * 8;
                int col = j0 + wn + ni * 8 + 2 * tq;
                float2 o = {acc[mi][ni][hh * 2], acc[mi][ni][hh * 2 + 1]};
                *(float2*)(out + ((size_t)bh * 512 + row) * 1024 + col) = o;
            }
}

// ---------------- flash attention: AC + BDr-gather + online softmax + PV -----
__global__ __launch_bounds__(128) void flash_attn(
    const float* __restrict__ qbase, const float* __restrict__ kbase,
    const float* __restrict__ vbase, const float* __restrict__ BDr,
    const float* __restrict__ rwb, __half* __restrict__ outh) {
    __shared__ unsigned sQ[64 * 68];
    __shared__ unsigned sKP[64 * 36];
    __shared__ unsigned sV[32 * 72];

    const int i0 = blockIdx.x * 64;
    const int bh = blockIdx.y;
    const int b = bh >> 4, h = bh & 15;
    const int t = threadIdx.x;
    const int lane = t & 31;
    const int wid = t >> 5;
    const int grp = lane >> 2, tq = lane & 3;
    const int wm = wid * 16;

    const float* qp = qbase + b * 3072 + h * 64;
    const float* kp = kbase + b * 3072 + h * 64;
    const float* vp = vbase + b * 3072 + h * 64;
    const float* bdp = BDr + (size_t)bh * QLEN * KLEN;

#pragma unroll
    for (int i = 0; i < 8; i++) {
        int f = t + 128 * i;
        int r = f >> 4;
        int c = (f & 15) << 2;
        float4 qv = *(const float4*)(qp + (size_t)(i0 + r) * 24576 + c);
        float4 bb = *(const float4*)(rwb + h * 64 + c);
        sQ[r * 68 + c + 0] = f2tf(qv.x + bb.x);
        sQ[r * 68 + c + 1] = f2tf(qv.y + bb.y);
        sQ[r * 68 + c + 2] = f2tf(qv.z + bb.z);
        sQ[r * 68 + c + 3] = f2tf(qv.w + bb.w);
    }

    const int r0g = i0 + wm + grp;
    const int r1g = r0g + 8;
    float m0 = -3e38f, m1 = -3e38f, l0 = 0.f, l1 = 0.f;
    float oacc[8][4] = {};

    const int njt = (i0 + 576) >> 5;
    for (int jt = 0; jt < njt; jt++) {
        const int j0 = jt * 32;
        __syncthreads();
#pragma unroll
        for (int i = 0; i < 4; i++) {
            int f = t + 128 * i;
            int r = f >> 4;
            int c = (f & 15) << 2;
            float4 kv = *(const float4*)(kp + (size_t)(j0 + r) * 24576 + c);
            sKP[r * 68 + c + 0] = f2tf(kv.x);
            sKP[r * 68 + c + 1] = f2tf(kv.y);
            sKP[r * 68 + c + 2] = f2tf(kv.z);
            sKP[r * 68 + c + 3] = f2tf(kv.w);
            float4 vv = *(const float4*)(vp + (size_t)(j0 + r) * 24576 + c);
            sV[r * 72 + c + 0] = f2tf(vv.x);
            sV[r * 72 + c + 1] = f2tf(vv.y);
            sV[r * 72 + c + 2] = f2tf(vv.z);
            sV[r * 72 + c + 3] = f2tf(vv.w);
        }
        __syncthreads();

        float sacc[4][4] = {};
#pragma unroll
        for (int ks = 0; ks < 8; ks++) {
            int k = ks * 8 + tq;
            unsigned a[4];
            a[0] = sQ[(wm + grp) * 68 + k];
            a[1] = sQ[(wm + grp + 8) * 68 + k];
            a[2] = sQ[(wm + grp) * 68 + k + 4];
            a[3] = sQ[(wm + grp + 8) * 68 + k + 4];
#pragma unroll
            for (int ni = 0; ni < 4; ni++) {
                unsigned bfr[2];
                bfr[0] = sKP[(ni * 8 + grp) * 68 + k];
                bfr[1] = sKP[(ni * 8 + grp) * 68 + k + 4];
                mma8(sacc[ni], a, bfr);
            }
        }

        float sv[4][4];
#pragma unroll
        for (int ni = 0; ni < 4; ni++)
#pragma unroll
            for (int v = 0; v < 4; v++) {
                int jg = j0 + ni * 8 + 2 * tq + (v & 1);
                int ig = (v < 2) ? r0g : r1g;
                float x = -3e38f;
                if (jg <= ig + 512) {
                    float bd = __ldg(bdp + (size_t)ig * KLEN + (jg + 511 - ig));
                    x = (sacc[ni][v] + bd) * 0.125f;
                }
                sv[ni][v] = x;
            }

        float rm0 = -3e38f, rm1 = -3e38f;
#pragma unroll
        for (int ni = 0; ni < 4; ni++) {
            rm0 = fmaxf(rm0, fmaxf(sv[ni][0], sv[ni][1]));
            rm1 = fmaxf(rm1, fmaxf(sv[ni][2], sv[ni][3]));
        }
        rm0 = fmaxf(rm0, __shfl_xor_sync(0xffffffff, rm0, 1));
        rm0 = fmaxf(rm0, __shfl_xor_sync(0xffffffff, rm0, 2));
        rm1 = fmaxf(rm1, __shfl_xor_sync(0xffffffff, rm1, 1));
        rm1 = fmaxf(rm1, __shfl_xor_sync(0xffffffff, rm1, 2));
        float mn0 = fmaxf(m0, rm0), mn1 = fmaxf(m1, rm1);
        float c0 = exp2f((m0 - mn0) * 1.44269504f);
        float c1 = exp2f((m1 - mn1) * 1.44269504f);
        float rs0 = 0.f, rs1 = 0.f;
#pragma unroll
        for (int ni = 0; ni < 4; ni++) {
            sv[ni][0] = exp2f((sv[ni][0] - mn0) * 1.44269504f);
            sv[ni][1] = exp2f((sv[ni][1] - mn0) * 1.44269504f);
            sv[ni][2] = exp2f((sv[ni][2] - mn1) * 1.44269504f);
            sv[ni][3] = exp2f((sv[ni][3] - mn1) * 1.44269504f);
            rs0 += sv[ni][0] + sv[ni][1];
            rs1 += sv[ni][2] + sv[ni][3];
        }
        rs0 += __shfl_xor_sync(0xffffffff, rs0, 1);
        rs0 += __shfl_xor_sync(0xffffffff, rs0, 2);
        rs1 += __shfl_xor_sync(0xffffffff, rs1, 1);
        rs1 += __shfl_xor_sync(0xffffffff, rs1, 2);
        l0 = l0 * c0 + rs0;
        l1 = l1 * c1 + rs1;
        m0 = mn0; m1 = mn1;
#pragma unroll
        for (int ni = 0; ni < 8; ni++) {
            oacc[ni][0] *= c0; oacc[ni][1] *= c0;
            oacc[ni][2] *= c1; oacc[ni][3] *= c1;
        }

        __syncthreads();
#pragma unroll
        for (int ni = 0; ni < 4; ni++) {
            int col = ni * 8 + 2 * tq;
            sKP[(wm + grp) * 36 + col] = f2tf(sv[ni][0]);
            sKP[(wm + grp) * 36 + col + 1] = f2tf(sv[ni][1]);
            sKP[(wm + grp + 8) * 36 + col] = f2tf(sv[ni][2]);
            sKP[(wm + grp + 8) * 36 + col + 1] = f2tf(sv[ni][3]);
        }
        __syncwarp();

#pragma unroll
        for (int ks = 0; ks < 4; ks++) {
            int k = ks * 8 + tq;
            unsigned a[4];
            a[0] = sKP[(wm + grp) * 36 + k];
            a[1] = sKP[(wm + grp + 8) * 36 + k];
            a[2] = sKP[(wm + grp) * 36 + k + 4];
            a[3] = sKP[(wm + grp + 8) * 36 + k + 4];
#pragma unroll
            for (int ni = 0; ni < 8; ni++) {
                unsigned bfr[2];
                bfr[0] = sV[(ks * 8 + tq) * 72 + ni * 8 + grp];
                bfr[1] = sV[(ks * 8 + tq + 4) * 72 + ni * 8 + grp];
                mma8(oacc[ni], a, bfr);
            }
        }
    }

    float inv0 = 1.f / l0, inv1 = 1.f / l1;
#pragma unroll
    for (int ni = 0; ni < 8; ni++) {
        int d = ni * 8 + 2 * tq;
        unsigned h0 = f2h2(oacc[ni][0] * inv0, oacc[ni][1] * inv0);
        unsigned h1v = f2h2(oacc[ni][2] * inv1, oacc[ni][3] * inv1);
        *(unsigned*)(outh + ((size_t)r0g * 8 + b) * 1024 + h * 64 + d) = h0;
        *(unsigned*)(outh + ((size_t)r1g * 8 + b) * 1024 + h * 64 + d) = h1v;
    }
}

// ---------------- residual + layernorm (fp32 out + fp16 copy) ----------------
__global__ __launch_bounds__(256) void resid_ln_kernel(
    const float* __restrict__ x, const float* __restrict__ y,
    const float* __restrict__ g, const float* __restrict__ bta,
    float* __restrict__ out, __half* __restrict__ outh) {
    __shared__ float red[256];
    int row = blockIdx.x, t = threadIdx.x;
    const float* xr = x + (size_t)row * 1024;
    const float* yr = y + (size_t)row * 1024;
    float v[4];
    float s = 0.f;
#pragma unroll
    for (int e = 0; e < 4; e++) {
        int c = t + 256 * e;
        v[e] = xr[c] + yr[c];
        s += v[e];
    }
    red[t] = s;
    __syncthreads();
    for (int w = 128; w > 0; w >>= 1) {
        if (t < w) red[t] += red[t + w];
        __syncthreads();
    }
    float mean = red[0] * (1.f / 1024.f);
    __syncthreads();
    float s2 = 0.f;
#pragma unroll
    for (int e = 0; e < 4; e++) {
        float d = v[e] - mean;
        s2 += d * d;
    }
    red[t] = s2;
    __syncthreads();
    for (int w = 128; w > 0; w >>= 1) {
        if (t < w) red[t] += red[t + w];
        __syncthreads();
    }
    float inv = rsqrtf(red[0] * (1.f / 1024.f) + 1e-5f);
#pragma unroll
    for (int e = 0; e < 4; e++) {
        int c = t + 256 * e;
        float o = (v[e] - mean) * inv * g[c] + bta[c];
        out[(size_t)row * 1024 + c] = o;
        outh[(size_t)row * 1024 + c] = __float2half(o);
    }
}

// ---------------- host orchestration ----------------
extern "C" void kernel_launch(void* const* d_in, const int* in_sizes, int n_in,
                              void* d_out, int out_size) {
    const int* inp = (const int*)d_in[0];
    const float* mems = (const float*)d_in[1];
    const float* emb_table = (const float*)d_in[2];
    const float* r_w_bias = (const float*)d_in[3];
    const float* r_r_bias = (const float*)d_in[4];
    const float* qkv_w = (const float*)d_in[5];
    const float* r_w = (const float*)d_in[6];
    const float* o_w = (const float*)d_in[7];
    const float* ln1_g = (const float*)d_in[8];
    const float* ln1_b = (const float*)d_in[9];
    const float* ff_w1 = (const float*)d_in[10];
    const float* ff_b1 = (const float*)d_in[11];
    const float* ff_w2 = (const float*)d_in[12];
    const float* ff_b2 = (const float*)d_in[13];
    const float* ln2_g = (const float*)d_in[14];
    const float* ln2_b = (const float*)d_in[15];

    void* p;
    cudaGetSymbolAddress(&p, g_core);    float* corep = (float*)p;
    cudaGetSymbolAddress(&p, g_heads);   float* headsp = (float*)p;
    cudaGetSymbolAddress(&p, g_BDr);     float* bdrp = (float*)p;
    cudaGetSymbolAddress(&p, g_attnout); float* aoutp = (float*)p;
    cudaGetSymbolAddress(&p, g_ff);      float* ffp = (float*)p;
    cudaGetSymbolAddress(&p, g_cath);    __half* cathp = (__half*)p;
    cudaGetSymbolAddress(&p, g_pemh);    __half* pemhp = (__half*)p;
    cudaGetSymbolAddress(&p, g_rkh);     __half* rkhp = (__half*)p;
    cudaGetSymbolAddress(&p, g_coreh);   __half* corehp = (__half*)p;
    cudaGetSymbolAddress(&p, g_avech);   __half* avechp = (__half*)p;
    cudaGetSymbolAddress(&p, g_h1h);     __half* h1hp = (__half*)p;
    cudaGetSymbolAddress(&p, g_qkvwh);   __half* qkvwhp = (__half*)p;
    cudaGetSymbolAddress(&p, g_rwh);     __half* rwhp = (__half*)p;
    cudaGetSymbolAddress(&p, g_owh);     __half* owhp = (__half*)p;
    cudaGetSymbolAddress(&p, g_w1h);     __half* w1hp = (__half*)p;
    cudaGetSymbolAddress(&p, g_w2h);     __half* w2hp = (__half*)p;

    const size_t CORE_BYTES = (size_t)QLEN * BSZ * DMODEL * sizeof(float);

    // weight conversions (once per launch)
    {
        int n;
        n = 4 * 3 * DMODEL * DMODEL / 4;
        w2h_kernel<<<n / 256, 256>>>(qkv_w, qkvwhp, n);
        n = 4 * DMODEL * DMODEL / 4;
        w2h_kernel<<<n / 256, 256>>>(r_w, rwhp, n);
        w2h_kernel<<<n / 256, 256>>>(o_w, owhp, n);
        n = 4 * DINNER * DMODEL / 4;
        w2h_kernel<<<n / 256, 256>>>(ff_w1, w1hp, n);
        w2h_kernel<<<n / 256, 256>>>(ff_w2, w2hp, n);
    }

    embed_kernel<<<QLEN * BSZ, 256>>>(inp, emb_table, corep);
    posemb_kernel<<<KLEN, 512>>>(pemhp);

    for (int l = 0; l < 4; l++) {
        // cat_h = fp16([mems[l]; core])
        cat_f16_kernel<<<KLEN * BSZ, 256>>>(
            mems + (size_t)l * MLEN * BSZ * DMODEL, corep, cathp);
        // heads = cat @ qkv_w[l]^T   (8192 x 3072 x 1024) fp32 out
        gemm_nt_h<false, false, false><<<dim3(24, 64), 256>>>(
            cathp, qkvwhp + (size_t)l * 3 * DMODEL * DMODEL, nullptr,
            headsp, nullptr, KLEN * BSZ, 3 * DMODEL, DMODEL);
        // rk = pos_emb @ r_w[l]^T    (1024 x 1024 x 1024) fp16 out
        gemm_nt_h<false, false, true><<<dim3(8, 8), 256>>>(
            pemhp, rwhp + (size_t)l * DMODEL * DMODEL, nullptr,
            nullptr, rkhp, KLEN, DMODEL, DMODEL);
        // BDr = (q + r_r_bias) . rk
        qk_f16<<<dim3(16, 8, 128), 256>>>(
            headsp + (size_t)MLEN * BSZ * 3 * DMODEL, rkhp, r_r_bias, bdrp);
        // flash attention -> avec (fp16)
        flash_attn<<<dim3(8, 128), 128>>>(
            headsp + (size_t)MLEN * BSZ * 3 * DMODEL, headsp + DMODEL,
            headsp + 2 * DMODEL, bdrp, r_w_bias, avechp);
        // attn_out = attn_vec @ o_w[l]^T   (4096 x 1024 x 1024) fp32 out
        gemm_nt_h<false, false, false><<<dim3(8, 32), 256>>>(
            avechp, owhp + (size_t)l * DMODEL * DMODEL, nullptr,
            aoutp, nullptr, QLEN * BSZ, DMODEL, DMODEL);
        resid_ln_kernel<<<QLEN * BSZ, 256>>>(corep, aoutp, ln1_g + l * DMODEL,
                                             ln1_b + l * DMODEL, corep, corehp);
        // h1 = relu(core @ ff_w1^T + b1)   (4096 x 4096 x 1024) fp16 out
        gemm_nt_h<true, true, true><<<dim3(32, 32), 256>>>(
            corehp, w1hp + (size_t)l * DINNER * DMODEL, ff_b1 + l * DINNER,
            nullptr, h1hp, QLEN * BSZ, DINNER, DMODEL);
        // ff = h1 @ ff_w2^T + b2           (4096 x 1024 x 4096) fp32 out
        gemm_nt_h<false, true, false><<<dim3(8, 32), 256>>>(
            h1hp, w2hp + (size_t)l * DMODEL * DINNER, ff_b2 + l * DMODEL,
            ffp, nullptr, QLEN * BSZ, DMODEL, DINNER);
        resid_ln_kernel<<<QLEN * BSZ, 256>>>(corep, ffp, ln2_g + l * DMODEL,
                                             ln2_b + l * DMODEL, corep, corehp);
    }

    cudaMemcpyAsync(d_out, corep, CORE_BYTES, cudaMemcpyDeviceToDevice);
}

// round 11
// speedup vs baseline: 4.5709x; 1.1508x over previous
#include <cuda_runtime.h>
#include <cuda_fp16.h>

#define QLEN 512
#define MLEN 512
#define KLEN 1024
#define BSZ 8
#define DMODEL 1024
#define NHEAD 16
#define DHEAD 64
#define DINNER 4096

// ---------------- scratch (no allocations allowed) ----------------
__device__ float g_core[QLEN * BSZ * DMODEL];
__device__ float g_BDr[BSZ * NHEAD * QLEN * KLEN];
__device__ float g_attnout[QLEN * BSZ * DMODEL];
__device__ float g_ff[QLEN * BSZ * DMODEL];

__device__ __half g_headsh[KLEN * BSZ * 3 * DMODEL];
__device__ __half g_cath[KLEN * BSZ * DMODEL];
__device__ __half g_pemh[KLEN * DMODEL];
__device__ __half g_rkh[KLEN * DMODEL];
__device__ __half g_coreh[QLEN * BSZ * DMODEL];
__device__ __half g_avech[QLEN * BSZ * DMODEL];
__device__ __half g_h1h[QLEN * BSZ * DINNER];

__device__ __half g_qkvwh[4 * 3 * DMODEL * DMODEL];
__device__ __half g_rwh[4 * DMODEL * DMODEL];
__device__ __half g_owh[4 * DMODEL * DMODEL];
__device__ __half g_w1h[4 * DINNER * DMODEL];
__device__ __half g_w2h[4 * DMODEL * DINNER];

// ---------------- helpers ----------------
__device__ __forceinline__ unsigned f2h2(float a, float b) {
    __half2 h = __floats2half2_rn(a, b);
    return *(unsigned*)&h;
}

__device__ __forceinline__ void mma16(float* c, const unsigned* a,
                                      unsigned b0, unsigned b1) {
    asm volatile(
        "mma.sync.aligned.m16n8k16.row.col.f32.f16.f16.f32 "
        "{%0,%1,%2,%3}, {%4,%5,%6,%7}, {%8,%9}, {%0,%1,%2,%3};"
        : "+f"(c[0]), "+f"(c[1]), "+f"(c[2]), "+f"(c[3])
        : "r"(a[0]), "r"(a[1]), "r"(a[2]), "r"(a[3]), "r"(b0), "r"(b1));
}

__device__ __forceinline__ void ldsm4(unsigned* r, const __half* p) {
    unsigned addr = (unsigned)__cvta_generic_to_shared(p);
    asm volatile("ldmatrix.sync.aligned.m8n8.x4.shared.b16 {%0,%1,%2,%3}, [%4];"
                 : "=r"(r[0]), "=r"(r[1]), "=r"(r[2]), "=r"(r[3])
                 : "r"(addr));
}

__device__ __forceinline__ void ldsm4t(unsigned* r, const __half* p) {
    unsigned addr = (unsigned)__cvta_generic_to_shared(p);
    asm volatile("ldmatrix.sync.aligned.m8n8.x4.trans.shared.b16 {%0,%1,%2,%3}, [%4];"
                 : "=r"(r[0]), "=r"(r[1]), "=r"(r[2]), "=r"(r[3])
                 : "r"(addr));
}

// ---------------- weight fp32 -> fp16 ----------------
__global__ void w2h_kernel(const float* __restrict__ src, __half* __restrict__ dst,
                           int n4) {
    int i = blockIdx.x * 256 + threadIdx.x;
    if (i < n4) {
        float4 v = ((const float4*)src)[i];
        uint2 o = make_uint2(f2h2(v.x, v.y), f2h2(v.z, v.w));
        *(uint2*)(dst + (size_t)i * 4) = o;
    }
}

// ---------------- embedding lookup: core = emb[inp] * sqrt(D) ----------------
__global__ void embed_kernel(const int* __restrict__ inp,
                             const float* __restrict__ emb,
                             float* __restrict__ core) {
    int row = blockIdx.x;
    int tok = inp[row];
    const float4* src = (const float4*)(emb + (size_t)tok * DMODEL);
    float4* dst = (float4*)(core + (size_t)row * DMODEL);
    float4 v = src[threadIdx.x];
    v.x *= 32.f; v.y *= 32.f; v.z *= 32.f; v.w *= 32.f;
    dst[threadIdx.x] = v;
}

// ---------------- cat (fp16) = [mems_l ; core] ----------------
__global__ void cat_f16_kernel(const float* __restrict__ mems_l,
                               const float* __restrict__ core,
                               __half* __restrict__ cath) {
    int row = blockIdx.x;
    int t = threadIdx.x;
    const float* s = (row < MLEN * BSZ) ? mems_l + (size_t)row * DMODEL
                                        : core + (size_t)(row - MLEN * BSZ) * DMODEL;
    float4 v = ((const float4*)s)[t];
    uint2 o = make_uint2(f2h2(v.x, v.y), f2h2(v.z, v.w));
    *(uint2*)(cath + (size_t)row * DMODEL + t * 4) = o;
}

// ---------------- sinusoidal positional embedding (fp16) ----------------
__global__ void posemb_kernel(__half* __restrict__ pe) {
    int k = blockIdx.x;
    int j = threadIdx.x;
    double invf = exp(-(2.0 * (double)j / 1024.0) * log(10000.0));
    double ang = (double)(KLEN - 1 - k) * invf;
    pe[(size_t)k * DMODEL + j] = __float2half((float)sin(ang));
    pe[(size_t)k * DMODEL + 512 + j] = __float2half((float)cos(ang));
}

// ---------------- NT GEMM: fp16 A/B in gmem, LDG double-buffer + ldmatrix ----
template <bool RELU, bool HASBIAS, bool OUTF16>
__global__ __launch_bounds__(256, 2) void gemm_nt_h(
    const __half* __restrict__ A, const __half* __restrict__ B,
    const float* __restrict__ bias, float* __restrict__ C,
    __half* __restrict__ Ch, int M, int N, int K) {
    __shared__ __align__(16) __half sA[2][128 * 40];
    __shared__ __align__(16) __half sB[2][128 * 40];
    const int t = threadIdx.x;
    const int m0 = blockIdx.y * 128, n0 = blockIdx.x * 128;
    const int lane = t & 31, wid = t >> 5;
    const int grp = lane >> 2, tq = lane & 3;
    const int wm = (wid & 1) * 64, wn = (wid >> 1) * 32;
    const int l15 = lane & 15, lhi = (lane >> 4) * 8;
    const __half* Ab = A + (size_t)m0 * K;
    const __half* Bb = B + (size_t)n0 * K;

    int cr[2], cc[2];
#pragma unroll
    for (int i = 0; i < 2; i++) {
        int idx = t + 256 * i;
        cr[i] = idx >> 2;
        cc[i] = (idx & 3) * 8;
    }

    float acc[4][4][4] = {};
    const int NKT = K >> 5;
    uint4 pa[2], pb[2];

#pragma unroll
    for (int i = 0; i < 2; i++) {
        pa[i] = *(const uint4*)(Ab + (size_t)cr[i] * K + cc[i]);
        pb[i] = *(const uint4*)(Bb + (size_t)cr[i] * K + cc[i]);
    }

    for (int kt = 0; kt < NKT; kt++) {
        int s = kt & 1;
#pragma unroll
        for (int i = 0; i < 2; i++) {
            *(uint4*)&sA[s][cr[i] * 40 + cc[i]] = pa[i];
            *(uint4*)&sB[s][cr[i] * 40 + cc[i]] = pb[i];
        }
        __syncthreads();
        if (kt + 1 < NKT) {
            int kn = (kt + 1) * 32;
#pragma unroll
            for (int i = 0; i < 2; i++) {
                pa[i] = *(const uint4*)(Ab + (size_t)cr[i] * K + kn + cc[i]);
                pb[i] = *(const uint4*)(Bb + (size_t)cr[i] * K + kn + cc[i]);
            }
        }
        const __half* as = sA[s];
        const __half* bs = sB[s];
#pragma unroll
        for (int ks = 0; ks < 2; ks++) {
            unsigned af[4][4], bf[2][4];
#pragma unroll
            for (int mi = 0; mi < 4; mi++)
                ldsm4(af[mi], &as[(wm + mi * 16 + l15) * 40 + ks * 16 + lhi]);
#pragma unroll
            for (int nc = 0; nc < 2; nc++)
                ldsm4(bf[nc], &bs[(wn + nc * 16 + l15) * 40 + ks * 16 + lhi]);
#pragma unroll
            for (int mi = 0; mi < 4; mi++)
#pragma unroll
                for (int ni = 0; ni < 4; ni++) {
                    int nc = ni >> 1, w = ni & 1;
                    mma16(acc[mi][ni], af[mi], bf[nc][w], bf[nc][w + 2]);
                }
        }
    }

#pragma unroll
    for (int mi = 0; mi < 4; mi++)
#pragma unroll
        for (int ni = 0; ni < 4; ni++) {
            int col = n0 + wn + ni * 8 + 2 * tq;
            float b0 = 0.f, b1 = 0.f;
            if (HASBIAS) { b0 = __ldg(bias + col); b1 = __ldg(bias + col + 1); }
#pragma unroll
            for (int hh = 0; hh < 2; hh++) {
                int row = m0 + wm + mi * 16 + grp + hh * 8;
                float ox = acc[mi][ni][hh * 2 + 0] + b0;
                float oy = acc[mi][ni][hh * 2 + 1] + b1;
                if (RELU) { ox = fmaxf(ox, 0.f); oy = fmaxf(oy, 0.f); }
                if (OUTF16) {
                    unsigned hv = f2h2(ox, oy);
                    *(unsigned*)(Ch + (size_t)row * N + col) = hv;
                } else {
                    float2 o = {ox, oy};
                    *(float2*)(C + (size_t)row * N + col) = o;
                }
            }
        }
}

// ---------------- BDr = (q + r_r_bias) . rk^T  (fp16 mma, 64x64 tiles) ------
__global__ __launch_bounds__(256) void qk_f16(
    const __half* __restrict__ qbase, const __half* __restrict__ rkh,
    const float* __restrict__ bias, float* __restrict__ out) {
    __shared__ __align__(16) __half Qs[64 * 72];
    __shared__ __align__(16) __half Ks[64 * 72];
    int bh = blockIdx.z;
    int b = bh >> 4, h = bh & 15;
    int i0 = blockIdx.y * 64, j0 = blockIdx.x * 64;
    int t = threadIdx.x;
    const __half* qp = qbase + b * 3072 + h * 64;
    const __half* rkp = rkh + h * 64;   // per-head slice of rk (klen, H, dh)
    const float* bi = bias + h * 64;

#pragma unroll
    for (int i = 0; i < 2; i++) {
        int idx = t + 256 * i;       // 0..511
        int r = idx >> 3;            // 0..63
        int c = (idx & 7) * 8;       // 0..56
        uint4 qv = *(const uint4*)(qp + (size_t)(i0 + r) * 24576 + c);
        const __half* qh = (const __half*)&qv;
        float4 b0 = *(const float4*)(bi + c);
        float4 b1 = *(const float4*)(bi + c + 4);
        uint4 o = make_uint4(
            f2h2(__half2float(qh[0]) + b0.x, __half2float(qh[1]) + b0.y),
            f2h2(__half2float(qh[2]) + b0.z, __half2float(qh[3]) + b0.w),
            f2h2(__half2float(qh[4]) + b1.x, __half2float(qh[5]) + b1.y),
            f2h2(__half2float(qh[6]) + b1.z, __half2float(qh[7]) + b1.w));
        *(uint4*)&Qs[r * 72 + c] = o;
        *(uint4*)&Ks[r * 72 + c] = *(const uint4*)(rkp + (size_t)(j0 + r) * DMODEL + c);
    }
    __syncthreads();

    int lane = t & 31, wid = t >> 5;
    int grp = lane >> 2, tq = lane & 3;
    int l15 = lane & 15, lhi = (lane >> 4) * 8;
    int wm = (wid & 1) * 32, wn = (wid >> 1) * 16;
    float acc[2][2][4] = {};

#pragma unroll
    for (int ks = 0; ks < 4; ks++) {
        unsigned af[2][4], bf[4];
#pragma unroll
        for (int mi = 0; mi < 2; mi++)
            ldsm4(af[mi], &Qs[(wm + mi * 16 + l15) * 72 + ks * 16 + lhi]);
        ldsm4(bf, &Ks[(wn + l15) * 72 + ks * 16 + lhi]);
#pragma unroll
        for (int mi = 0; mi < 2; mi++)
#pragma unroll
            for (int ni = 0; ni < 2; ni++)
                mma16(acc[mi][ni], af[mi], bf[ni], bf[ni + 2]);
    }

#pragma unroll
    for (int mi = 0; mi < 2; mi++)
#pragma unroll
        for (int ni = 0; ni < 2; ni++)
#pragma unroll
            for (int hh = 0; hh < 2; hh++) {
                int row = i0 + wm + mi * 16 + grp + hh * 8;
                int col = j0 + wn + ni * 8 + 2 * tq;
                float2 o = {acc[mi][ni][hh * 2], acc[mi][ni][hh * 2 + 1]};
                *(float2*)(out + ((size_t)bh * 512 + row) * 1024 + col) = o;
            }
}

// ---------------- flash attention (fp16 + ldmatrix) --------------------------
// Block: 128 threads (4 warps); warp owns 16 query rows; 64 q-rows per block.
__global__ __launch_bounds__(128) void flash_attn(
    const __half* __restrict__ qbase, const __half* __restrict__ kbase,
    const __half* __restrict__ vbase, const float* __restrict__ BDr,
    const float* __restrict__ rwb, __half* __restrict__ outh) {
    __shared__ __align__(16) __half sQ[64 * 72];
    __shared__ __align__(16) __half sK[32 * 72];
    __shared__ __align__(16) __half sV[32 * 72];
    __shared__ __align__(16) __half sP[64 * 40];

    const int i0 = blockIdx.x * 64;
    const int bh = blockIdx.y;
    const int b = bh >> 4, h = bh & 15;
    const int t = threadIdx.x;
    const int lane = t & 31;
    const int wid = t >> 5;
    const int grp = lane >> 2, tq = lane & 3;
    const int l15 = lane & 15, lhi = (lane >> 4) * 8;
    const int wm = wid * 16;

    const __half* qp = qbase + b * 3072 + h * 64;
    const __half* kp = kbase + b * 3072 + h * 64;
    const __half* vp = vbase + b * 3072 + h * 64;
    const float* bdp = BDr + (size_t)bh * QLEN * KLEN;

    // load Q + r_w_bias (64 rows x 64 halfs = 512 uint4, 4 per thread)
#pragma unroll
    for (int i = 0; i < 4; i++) {
        int idx = t + 128 * i;
        int r = idx >> 3;            // 0..63
        int c = (idx & 7) * 8;       // 0..56
        uint4 qv = *(const uint4*)(qp + (size_t)(i0 + r) * 24576 + c);
        const __half* qh = (const __half*)&qv;
        float4 b0 = *(const float4*)(rwb + h * 64 + c);
        float4 b1 = *(const float4*)(rwb + h * 64 + c + 4);
        uint4 o = make_uint4(
            f2h2(__half2float(qh[0]) + b0.x, __half2float(qh[1]) + b0.y),
            f2h2(__half2float(qh[2]) + b0.z, __half2float(qh[3]) + b0.w),
            f2h2(__half2float(qh[4]) + b1.x, __half2float(qh[5]) + b1.y),
            f2h2(__half2float(qh[6]) + b1.z, __half2float(qh[7]) + b1.w));
        *(uint4*)&sQ[r * 72 + c] = o;
    }

    const int r0g = i0 + wm + grp;
    const int r1g = r0g + 8;
    float m0 = -3e38f, m1 = -3e38f, l0 = 0.f, l1 = 0.f;
    float oacc[8][4] = {};

    const int njt = (i0 + 576) >> 5;
    for (int jt = 0; jt < njt; jt++) {
        const int j0 = jt * 32;
        __syncthreads();  // prior readers of sK/sV done (covers sQ on iter 0)
        // load K, V (32 rows x 64 halfs = 256 uint4 each, 2 per thread)
#pragma unroll
        for (int i = 0; i < 2; i++) {
            int idx = t + 128 * i;
            int r = idx >> 3;        // 0..31
            int c = (idx & 7) * 8;   // 0..56
            *(uint4*)&sK[r * 72 + c] = *(const uint4*)(kp + (size_t)(j0 + r) * 24576 + c);
            *(uint4*)&sV[r * 72 + c] = *(const uint4*)(vp + (size_t)(j0 + r) * 24576 + c);
        }
        __syncthreads();

        // AC = Qw . K^T  (warp: 16 rows x 32 cols, K=64 -> 4 ksteps)
        float sacc[4][4] = {};
#pragma unroll
        for (int ks = 0; ks < 4; ks++) {
            unsigned a[4], bf0[4], bf1[4];
            ldsm4(a, &sQ[(wm + l15) * 72 + ks * 16 + lhi]);
            ldsm4(bf0, &sK[l15 * 72 + ks * 16 + lhi]);
            ldsm4(bf1, &sK[(16 + l15) * 72 + ks * 16 + lhi]);
            mma16(sacc[0], a, bf0[0], bf0[2]);
            mma16(sacc[1], a, bf0[1], bf0[3]);
            mma16(sacc[2], a, bf1[0], bf1[2]);
            mma16(sacc[3], a, bf1[1], bf1[3]);
        }

        // gather shifted BDr, scale, mask
        float sv[4][4];
#pragma unroll
        for (int ni = 0; ni < 4; ni++)
#pragma unroll
            for (int v = 0; v < 4; v++) {
                int jg = j0 + ni * 8 + 2 * tq + (v & 1);
                int ig = (v < 2) ? r0g : r1g;
                float x = -3e38f;
                if (jg <= ig + 512) {
                    float bd = __ldg(bdp + (size_t)ig * KLEN + (jg + 511 - ig));
                    x = (sacc[ni][v] + bd) * 0.125f;
                }
                sv[ni][v] = x;
            }

        // warp-local online softmax
        float rm0 = -3e38f, rm1 = -3e38f;
#pragma unroll
        for (int ni = 0; ni < 4; ni++) {
            rm0 = fmaxf(rm0, fmaxf(sv[ni][0], sv[ni][1]));
            rm1 = fmaxf(rm1, fmaxf(sv[ni][2], sv[ni][3]));
        }
        rm0 = fmaxf(rm0, __shfl_xor_sync(0xffffffff, rm0, 1));
        rm0 = fmaxf(rm0, __shfl_xor_sync(0xffffffff, rm0, 2));
        rm1 = fmaxf(rm1, __shfl_xor_sync(0xffffffff, rm1, 1));
        rm1 = fmaxf(rm1, __shfl_xor_sync(0xffffffff, rm1, 2));
        float mn0 = fmaxf(m0, rm0), mn1 = fmaxf(m1, rm1);
        float c0 = exp2f((m0 - mn0) * 1.44269504f);
        float c1 = exp2f((m1 - mn1) * 1.44269504f);
        float rs0 = 0.f, rs1 = 0.f;
#pragma unroll
        for (int ni = 0; ni < 4; ni++) {
            sv[ni][0] = exp2f((sv[ni][0] - mn0) * 1.44269504f);
            sv[ni][1] = exp2f((sv[ni][1] - mn0) * 1.44269504f);
            sv[ni][2] = exp2f((sv[ni][2] - mn1) * 1.44269504f);
            sv[ni][3] = exp2f((sv[ni][3] - mn1) * 1.44269504f);
            rs0 += sv[ni][0] + sv[ni][1];
            rs1 += sv[ni][2] + sv[ni][3];
        }
        rs0 += __shfl_xor_sync(0xffffffff, rs0, 1);
        rs0 += __shfl_xor_sync(0xffffffff, rs0, 2);
        rs1 += __shfl_xor_sync(0xffffffff, rs1, 1);
        rs1 += __shfl_xor_sync(0xffffffff, rs1, 2);
        l0 = l0 * c0 + rs0;
        l1 = l1 * c1 + rs1;
        m0 = mn0; m1 = mn1;
#pragma unroll
        for (int ni = 0; ni < 8; ni++) {
            oacc[ni][0] *= c0; oacc[ni][1] *= c0;
            oacc[ni][2] *= c1; oacc[ni][3] *= c1;
        }

        // write P (fp16) into sP (warp-private rows; no block barrier needed)
#pragma unroll
        for (int ni = 0; ni < 4; ni++) {
            int col = ni * 8 + 2 * tq;
            *(unsigned*)&sP[(wm + grp) * 40 + col] = f2h2(sv[ni][0], sv[ni][1]);
            *(unsigned*)&sP[(wm + grp + 8) * 40 + col] = f2h2(sv[ni][2], sv[ni][3]);
        }
        __syncwarp();

        // O += P . V  (K=32 -> 2 ksteps; V[j][d] loaded via ldmatrix.trans)
#pragma unroll
        for (int ks = 0; ks < 2; ks++) {
            unsigned a[4];
            ldsm4(a, &sP[(wm + l15) * 40 + ks * 16 + lhi]);
#pragma unroll
            for (int dg = 0; dg < 4; dg++) {
                unsigned bt[4];
                ldsm4t(bt, &sV[(ks * 16 + l15) * 72 + dg * 16 + lhi]);
                mma16(oacc[dg * 2 + 0], a, bt[0], bt[1]);
                mma16(oacc[dg * 2 + 1], a, bt[2], bt[3]);
            }
        }
    }

    // epilogue: normalize and store attn_vec (fp16)
    float inv0 = 1.f / l0, inv1 = 1.f / l1;
#pragma unroll
    for (int ni = 0; ni < 8; ni++) {
        int d = ni * 8 + 2 * tq;
        unsigned h0 = f2h2(oacc[ni][0] * inv0, oacc[ni][1] * inv0);
        unsigned h1v = f2h2(oacc[ni][2] * inv1, oacc[ni][3] * inv1);
        *(unsigned*)(outh + ((size_t)r0g * 8 + b) * 1024 + h * 64 + d) = h0;
        *(unsigned*)(outh + ((size_t)r1g * 8 + b) * 1024 + h * 64 + d) = h1v;
    }
}

// ---------------- residual + layernorm (fp32 out + fp16 copy) ----------------
__global__ __launch_bounds__(256) void resid_ln_kernel(
    const float* __restrict__ x, const float* __restrict__ y,
    const float* __restrict__ g, const float* __restrict__ bta,
    float* __restrict__ out, __half* __restrict__ outh) {
    __shared__ float red[256];
    int row = blockIdx.x, t = threadIdx.x;
    const float* xr = x + (size_t)row * 1024;
    const float* yr = y + (size_t)row * 1024;
    float v[4];
    float s = 0.f;
#pragma unroll
    for (int e = 0; e < 4; e++) {
        int c = t + 256 * e;
        v[e] = xr[c] + yr[c];
        s += v[e];
    }
    red[t] = s;
    __syncthreads();
    for (int w = 128; w > 0; w >>= 1) {
        if (t < w) red[t] += red[t + w];
        __syncthreads();
    }
    float mean = red[0] * (1.f / 1024.f);
    __syncthreads();
    float s2 = 0.f;
#pragma unroll
    for (int e = 0; e < 4; e++) {
        float d = v[e] - mean;
        s2 += d * d;
    }
    red[t] = s2;
    __syncthreads();
    for (int w = 128; w > 0; w >>= 1) {
        if (t < w) red[t] += red[t + w];
        __syncthreads();
    }
    float inv = rsqrtf(red[0] * (1.f / 1024.f) + 1e-5f);
#pragma unroll
    for (int e = 0; e < 4; e++) {
        int c = t + 256 * e;
        float o = (v[e] - mean) * inv * g[c] + bta[c];
        out[(size_t)row * 1024 + c] = o;
        outh[(size_t)row * 1024 + c] = __float2half(o);
    }
}

// ---------------- host orchestration ----------------
extern "C" void kernel_launch(void* const* d_in, const int* in_sizes, int n_in,
                              void* d_out, int out_size) {
    const int* inp = (const int*)d_in[0];
    const float* mems = (const float*)d_in[1];
    const float* emb_table = (const float*)d_in[2];
    const float* r_w_bias = (const float*)d_in[3];
    const float* r_r_bias = (const float*)d_in[4];
    const float* qkv_w = (const float*)d_in[5];
    const float* r_w = (const float*)d_in[6];
    const float* o_w = (const float*)d_in[7];
    const float* ln1_g = (const float*)d_in[8];
    const float* ln1_b = (const float*)d_in[9];
    const float* ff_w1 = (const float*)d_in[10];
    const float* ff_b1 = (const float*)d_in[11];
    const float* ff_w2 = (const float*)d_in[12];
    const float* ff_b2 = (const float*)d_in[13];
    const float* ln2_g = (const float*)d_in[14];
    const float* ln2_b = (const float*)d_in[15];

    void* p;
    cudaGetSymbolAddress(&p, g_core);    float* corep = (float*)p;
    cudaGetSymbolAddress(&p, g_BDr);     float* bdrp = (float*)p;
    cudaGetSymbolAddress(&p, g_attnout); float* aoutp = (float*)p;
    cudaGetSymbolAddress(&p, g_ff);      float* ffp = (float*)p;
    cudaGetSymbolAddress(&p, g_headsh);  __half* headshp = (__half*)p;
    cudaGetSymbolAddress(&p, g_cath);    __half* cathp = (__half*)p;
    cudaGetSymbolAddress(&p, g_pemh);    __half* pemhp = (__half*)p;
    cudaGetSymbolAddress(&p, g_rkh);     __half* rkhp = (__half*)p;
    cudaGetSymbolAddress(&p, g_coreh);   __half* corehp = (__half*)p;
    cudaGetSymbolAddress(&p, g_avech);   __half* avechp = (__half*)p;
    cudaGetSymbolAddress(&p, g_h1h);     __half* h1hp = (__half*)p;
    cudaGetSymbolAddress(&p, g_qkvwh);   __half* qkvwhp = (__half*)p;
    cudaGetSymbolAddress(&p, g_rwh);     __half* rwhp = (__half*)p;
    cudaGetSymbolAddress(&p, g_owh);     __half* owhp = (__half*)p;
    cudaGetSymbolAddress(&p, g_w1h);     __half* w1hp = (__half*)p;
    cudaGetSymbolAddress(&p, g_w2h);     __half* w2hp = (__half*)p;

    const size_t CORE_BYTES = (size_t)QLEN * BSZ * DMODEL * sizeof(float);

    // weight conversions (once per launch)
    {
        int n;
        n = 4 * 3 * DMODEL * DMODEL / 4;
        w2h_kernel<<<n / 256, 256>>>(qkv_w, qkvwhp, n);
        n = 4 * DMODEL * DMODEL / 4;
        w2h_kernel<<<n / 256, 256>>>(r_w, rwhp, n);
        w2h_kernel<<<n / 256, 256>>>(o_w, owhp, n);
        n = 4 * DINNER * DMODEL / 4;
        w2h_kernel<<<n / 256, 256>>>(ff_w1, w1hp, n);
        w2h_kernel<<<n / 256, 256>>>(ff_w2, w2hp, n);
    }

    embed_kernel<<<QLEN * BSZ, 256>>>(inp, emb_table, corep);
    posemb_kernel<<<KLEN, 512>>>(pemhp);

    const __half* qh = headshp + (size_t)MLEN * BSZ * 3 * DMODEL;

    for (int l = 0; l < 4; l++) {
        // cat_h = fp16([mems[l]; core])
        cat_f16_kernel<<<KLEN * BSZ, 256>>>(
            mems + (size_t)l * MLEN * BSZ * DMODEL, corep, cathp);
        // heads = cat @ qkv_w[l]^T   (8192 x 3072 x 1024) fp16 out
        gemm_nt_h<false, false, true><<<dim3(24, 64), 256>>>(
            cathp, qkvwhp + (size_t)l * 3 * DMODEL * DMODEL, nullptr,
            nullptr, headshp, KLEN * BSZ, 3 * DMODEL, DMODEL);
        // rk = pos_emb @ r_w[l]^T    (1024 x 1024 x 1024) fp16 out
        gemm_nt_h<false, false, true><<<dim3(8, 8), 256>>>(
            pemhp, rwhp + (size_t)l * DMODEL * DMODEL, nullptr,
            nullptr, rkhp, KLEN, DMODEL, DMODEL);
        // BDr = (q + r_r_bias) . rk
        qk_f16<<<dim3(16, 8, 128), 256>>>(qh, rkhp, r_r_bias, bdrp);
        // flash attention -> avec (fp16)
        flash_attn<<<dim3(8, 128), 128>>>(
            qh, headshp + DMODEL, headshp + 2 * DMODEL, bdrp, r_w_bias, avechp);
        // attn_out = attn_vec @ o_w[l]^T   (4096 x 1024 x 1024) fp32 out
        gemm_nt_h<false, false, false><<<dim3(8, 32), 256>>>(
            avechp, owhp + (size_t)l * DMODEL * DMODEL, nullptr,
            aoutp, nullptr, QLEN * BSZ, DMODEL, DMODEL);
        resid_ln_kernel<<<QLEN * BSZ, 256>>>(corep, aoutp, ln1_g + l * DMODEL,
                                             ln1_b + l * DMODEL, corep, corehp);
        // h1 = relu(core @ ff_w1^T + b1)   (4096 x 4096 x 1024) fp16 out
        gemm_nt_h<true, true, true><<<dim3(32, 32), 256>>>(
            corehp, w1hp + (size_t)l * DINNER * DMODEL, ff_b1 + l * DINNER,
            nullptr, h1hp, QLEN * BSZ, DINNER, DMODEL);
        // ff = h1 @ ff_w2^T + b2           (4096 x 1024 x 4096) fp32 out
        gemm_nt_h<false, true, false><<<dim3(8, 32), 256>>>(
            h1hp, w2hp + (size_t)l * DMODEL * DINNER, ff_b2 + l * DMODEL,
            ffp, nullptr, QLEN * BSZ, DMODEL, DINNER);
        resid_ln_kernel<<<QLEN * BSZ, 256>>>(corep, ffp, ln2_g + l * DMODEL,
                                             ln2_b + l * DMODEL, corep, corehp);
    }

    cudaMemcpyAsync(d_out, corep, CORE_BYTES, cudaMemcpyDeviceToDevice);
}

// round 12
// speedup vs baseline: 4.6241x; 1.0116x over previous
#include <cuda_runtime.h>
#include <cuda_fp16.h>

#define QLEN 512
#define MLEN 512
#define KLEN 1024
#define BSZ 8
#define DMODEL 1024
#define NHEAD 16
#define DHEAD 64
#define DINNER 4096

// ---------------- scratch (no allocations allowed) ----------------
__device__ float g_core[QLEN * BSZ * DMODEL];
__device__ float g_attnout[QLEN * BSZ * DMODEL];
__device__ float g_ff[QLEN * BSZ * DMODEL];

__device__ __half g_BDrh[BSZ * NHEAD * QLEN * KLEN];
__device__ __half g_headsh[KLEN * BSZ * 3 * DMODEL];
__device__ __half g_cath[KLEN * BSZ * DMODEL];
__device__ __half g_pemh[KLEN * DMODEL];
__device__ __half g_rkh[KLEN * DMODEL];
__device__ __half g_coreh[QLEN * BSZ * DMODEL];
__device__ __half g_avech[QLEN * BSZ * DMODEL];
__device__ __half g_h1h[QLEN * BSZ * DINNER];

__device__ __half g_qkvwh[4 * 3 * DMODEL * DMODEL];
__device__ __half g_rwh[4 * DMODEL * DMODEL];
__device__ __half g_owh[4 * DMODEL * DMODEL];
__device__ __half g_w1h[4 * DINNER * DMODEL];
__device__ __half g_w2h[4 * DMODEL * DINNER];

// ---------------- helpers ----------------
__device__ __forceinline__ unsigned f2h2(float a, float b) {
    __half2 h = __floats2half2_rn(a, b);
    return *(unsigned*)&h;
}

__device__ __forceinline__ void mma16(float* c, const unsigned* a,
                                      unsigned b0, unsigned b1) {
    asm volatile(
        "mma.sync.aligned.m16n8k16.row.col.f32.f16.f16.f32 "
        "{%0,%1,%2,%3}, {%4,%5,%6,%7}, {%8,%9}, {%0,%1,%2,%3};"
        : "+f"(c[0]), "+f"(c[1]), "+f"(c[2]), "+f"(c[3])
        : "r"(a[0]), "r"(a[1]), "r"(a[2]), "r"(a[3]), "r"(b0), "r"(b1));
}

__device__ __forceinline__ void ldsm4(unsigned* r, const __half* p) {
    unsigned addr = (unsigned)__cvta_generic_to_shared(p);
    asm volatile("ldmatrix.sync.aligned.m8n8.x4.shared.b16 {%0,%1,%2,%3}, [%4];"
                 : "=r"(r[0]), "=r"(r[1]), "=r"(r[2]), "=r"(r[3])
                 : "r"(addr));
}

__device__ __forceinline__ void ldsm4t(unsigned* r, const __half* p) {
    unsigned addr = (unsigned)__cvta_generic_to_shared(p);
    asm volatile("ldmatrix.sync.aligned.m8n8.x4.trans.shared.b16 {%0,%1,%2,%3}, [%4];"
                 : "=r"(r[0]), "=r"(r[1]), "=r"(r[2]), "=r"(r[3])
                 : "r"(addr));
}

// ---------------- weight fp32 -> fp16 ----------------
__global__ void w2h_kernel(const float* __restrict__ src, __half* __restrict__ dst,
                           int n4) {
    int i = blockIdx.x * 256 + threadIdx.x;
    if (i < n4) {
        float4 v = ((const float4*)src)[i];
        uint2 o = make_uint2(f2h2(v.x, v.y), f2h2(v.z, v.w));
        *(uint2*)(dst + (size_t)i * 4) = o;
    }
}

// ---------------- embedding lookup: core = emb[inp] * sqrt(D) ----------------
__global__ void embed_kernel(const int* __restrict__ inp,
                             const float* __restrict__ emb,
                             float* __restrict__ core) {
    int row = blockIdx.x;
    int tok = inp[row];
    const float4* src = (const float4*)(emb + (size_t)tok * DMODEL);
    float4* dst = (float4*)(core + (size_t)row * DMODEL);
    float4 v = src[threadIdx.x];
    v.x *= 32.f; v.y *= 32.f; v.z *= 32.f; v.w *= 32.f;
    dst[threadIdx.x] = v;
}

// ---------------- cat (fp16) = [mems_l ; core] ----------------
__global__ void cat_f16_kernel(const float* __restrict__ mems_l,
                               const float* __restrict__ core,
                               __half* __restrict__ cath) {
    int row = blockIdx.x;
    int t = threadIdx.x;
    const float* s = (row < MLEN * BSZ) ? mems_l + (size_t)row * DMODEL
                                        : core + (size_t)(row - MLEN * BSZ) * DMODEL;
    float4 v = ((const float4*)s)[t];
    uint2 o = make_uint2(f2h2(v.x, v.y), f2h2(v.z, v.w));
    *(uint2*)(cath + (size_t)row * DMODEL + t * 4) = o;
}

// ---------------- sinusoidal positional embedding (fp16) ----------------
__global__ void posemb_kernel(__half* __restrict__ pe) {
    int k = blockIdx.x;
    int j = threadIdx.x;
    double invf = exp(-(2.0 * (double)j / 1024.0) * log(10000.0));
    double ang = (double)(KLEN - 1 - k) * invf;
    pe[(size_t)k * DMODEL + j] = __float2half((float)sin(ang));
    pe[(size_t)k * DMODEL + 512 + j] = __float2half((float)cos(ang));
}

// ---------------- NT GEMM: fp16 A/B in gmem, LDG double-buffer + ldmatrix ----
template <bool RELU, bool HASBIAS, bool OUTF16>
__global__ __launch_bounds__(256, 2) void gemm_nt_h(
    const __half* __restrict__ A, const __half* __restrict__ B,
    const float* __restrict__ bias, float* __restrict__ C,
    __half* __restrict__ Ch, int M, int N, int K) {
    __shared__ __align__(16) __half sA[2][128 * 40];
    __shared__ __align__(16) __half sB[2][128 * 40];
    const int t = threadIdx.x;
    const int m0 = blockIdx.y * 128, n0 = blockIdx.x * 128;
    const int lane = t & 31, wid = t >> 5;
    const int grp = lane >> 2, tq = lane & 3;
    const int wm = (wid & 1) * 64, wn = (wid >> 1) * 32;
    const int l15 = lane & 15, lhi = (lane >> 4) * 8;
    const __half* Ab = A + (size_t)m0 * K;
    const __half* Bb = B + (size_t)n0 * K;

    int cr[2], cc[2];
#pragma unroll
    for (int i = 0; i < 2; i++) {
        int idx = t + 256 * i;
        cr[i] = idx >> 2;
        cc[i] = (idx & 3) * 8;
    }

    float acc[4][4][4] = {};
    const int NKT = K >> 5;
    uint4 pa[2], pb[2];

#pragma unroll
    for (int i = 0; i < 2; i++) {
        pa[i] = *(const uint4*)(Ab + (size_t)cr[i] * K + cc[i]);
        pb[i] = *(const uint4*)(Bb + (size_t)cr[i] * K + cc[i]);
    }

    for (int kt = 0; kt < NKT; kt++) {
        int s = kt & 1;
#pragma unroll
        for (int i = 0; i < 2; i++) {
            *(uint4*)&sA[s][cr[i] * 40 + cc[i]] = pa[i];
            *(uint4*)&sB[s][cr[i] * 40 + cc[i]] = pb[i];
        }
        __syncthreads();
        if (kt + 1 < NKT) {
            int kn = (kt + 1) * 32;
#pragma unroll
            for (int i = 0; i < 2; i++) {
                pa[i] = *(const uint4*)(Ab + (size_t)cr[i] * K + kn + cc[i]);
                pb[i] = *(const uint4*)(Bb + (size_t)cr[i] * K + kn + cc[i]);
            }
        }
        const __half* as = sA[s];
        const __half* bs = sB[s];
#pragma unroll
        for (int ks = 0; ks < 2; ks++) {
            unsigned af[4][4], bf[2][4];
#pragma unroll
            for (int mi = 0; mi < 4; mi++)
                ldsm4(af[mi], &as[(wm + mi * 16 + l15) * 40 + ks * 16 + lhi]);
#pragma unroll
            for (int nc = 0; nc < 2; nc++)
                ldsm4(bf[nc], &bs[(wn + nc * 16 + l15) * 40 + ks * 16 + lhi]);
#pragma unroll
            for (int mi = 0; mi < 4; mi++)
#pragma unroll
                for (int ni = 0; ni < 4; ni++) {
                    int nc = ni >> 1, w = ni & 1;
                    mma16(acc[mi][ni], af[mi], bf[nc][w], bf[nc][w + 2]);
                }
        }
    }

#pragma unroll
    for (int mi = 0; mi < 4; mi++)
#pragma unroll
        for (int ni = 0; ni < 4; ni++) {
            int col = n0 + wn + ni * 8 + 2 * tq;
            float b0 = 0.f, b1 = 0.f;
            if (HASBIAS) { b0 = __ldg(bias + col); b1 = __ldg(bias + col + 1); }
#pragma unroll
            for (int hh = 0; hh < 2; hh++) {
                int row = m0 + wm + mi * 16 + grp + hh * 8;
                float ox = acc[mi][ni][hh * 2 + 0] + b0;
                float oy = acc[mi][ni][hh * 2 + 1] + b1;
                if (RELU) { ox = fmaxf(ox, 0.f); oy = fmaxf(oy, 0.f); }
                if (OUTF16) {
                    unsigned hv = f2h2(ox, oy);
                    *(unsigned*)(Ch + (size_t)row * N + col) = hv;
                } else {
                    float2 o = {ox, oy};
                    *(float2*)(C + (size_t)row * N + col) = o;
                }
            }
        }
}

// ---------------- BDr = (q + r_r_bias) . rk^T  (fp16 mma -> fp16 out) -------
// Tiles with i0 + u0 < 385 are never read by flash (u >= 511 - i) -> skip.
__global__ __launch_bounds__(256) void qk_f16(
    const __half* __restrict__ qbase, const __half* __restrict__ rkh,
    const float* __restrict__ bias, __half* __restrict__ out) {
    int bh = blockIdx.z;
    int b = bh >> 4, h = bh & 15;
    int i0 = blockIdx.y * 64, j0 = blockIdx.x * 64;
    if (i0 + j0 < 385) return;   // fully-masked BDr tile: never read
    __shared__ __align__(16) __half Qs[64 * 72];
    __shared__ __align__(16) __half Ks[64 * 72];
    int t = threadIdx.x;
    const __half* qp = qbase + b * 3072 + h * 64;
    const __half* rkp = rkh + h * 64;   // per-head slice of rk (klen, H, dh)
    const float* bi = bias + h * 64;

#pragma unroll
    for (int i = 0; i < 2; i++) {
        int idx = t + 256 * i;       // 0..511
        int r = idx >> 3;            // 0..63
        int c = (idx & 7) * 8;       // 0..56
        uint4 qv = *(const uint4*)(qp + (size_t)(i0 + r) * 24576 + c);
        const __half* qh = (const __half*)&qv;
        float4 b0 = *(const float4*)(bi + c);
        float4 b1 = *(const float4*)(bi + c + 4);
        uint4 o = make_uint4(
            f2h2(__half2float(qh[0]) + b0.x, __half2float(qh[1]) + b0.y),
            f2h2(__half2float(qh[2]) + b0.z, __half2float(qh[3]) + b0.w),
            f2h2(__half2float(qh[4]) + b1.x, __half2float(qh[5]) + b1.y),
            f2h2(__half2float(qh[6]) + b1.z, __half2float(qh[7]) + b1.w));
        *(uint4*)&Qs[r * 72 + c] = o;
        *(uint4*)&Ks[r * 72 + c] = *(const uint4*)(rkp + (size_t)(j0 + r) * DMODEL + c);
    }
    __syncthreads();

    int lane = t & 31, wid = t >> 5;
    int grp = lane >> 2, tq = lane & 3;
    int l15 = lane & 15, lhi = (lane >> 4) * 8;
    int wm = (wid & 1) * 32, wn = (wid >> 1) * 16;
    float acc[2][2][4] = {};

#pragma unroll
    for (int ks = 0; ks < 4; ks++) {
        unsigned af[2][4], bf[4];
#pragma unroll
        for (int mi = 0; mi < 2; mi++)
            ldsm4(af[mi], &Qs[(wm + mi * 16 + l15) * 72 + ks * 16 + lhi]);
        ldsm4(bf, &Ks[(wn + l15) * 72 + ks * 16 + lhi]);
#pragma unroll
        for (int mi = 0; mi < 2; mi++)
#pragma unroll
            for (int ni = 0; ni < 2; ni++)
                mma16(acc[mi][ni], af[mi], bf[ni], bf[ni + 2]);
    }

#pragma unroll
    for (int mi = 0; mi < 2; mi++)
#pragma unroll
        for (int ni = 0; ni < 2; ni++)
#pragma unroll
            for (int hh = 0; hh < 2; hh++) {
                int row = i0 + wm + mi * 16 + grp + hh * 8;
                int col = j0 + wn + ni * 8 + 2 * tq;
                unsigned hv = f2h2(acc[mi][ni][hh * 2], acc[mi][ni][hh * 2 + 1]);
                *(unsigned*)(out + ((size_t)bh * 512 + row) * 1024 + col) = hv;
            }
}

// ---------------- flash attention (fp16 + ldmatrix), 128 q-rows/block --------
// Block: 256 threads (8 warps), each warp owns 16 query rows.
__global__ __launch_bounds__(256) void flash_attn(
    const __half* __restrict__ qbase, const __half* __restrict__ kbase,
    const __half* __restrict__ vbase, const __half* __restrict__ BDr,
    const float* __restrict__ rwb, __half* __restrict__ outh) {
    __shared__ __align__(16) __half sQ[128 * 72];
    __shared__ __align__(16) __half sK[32 * 72];
    __shared__ __align__(16) __half sV[32 * 72];
    __shared__ __align__(16) __half sP[128 * 40];

    const int i0 = blockIdx.x * 128;
    const int bh = blockIdx.y;
    const int b = bh >> 4, h = bh & 15;
    const int t = threadIdx.x;
    const int lane = t & 31;
    const int wid = t >> 5;              // 0..7
    const int grp = lane >> 2, tq = lane & 3;
    const int l15 = lane & 15, lhi = (lane >> 4) * 8;
    const int wm = wid * 16;             // 0..112

    const __half* qp = qbase + b * 3072 + h * 64;
    const __half* kp = kbase + b * 3072 + h * 64;
    const __half* vp = vbase + b * 3072 + h * 64;
    const __half* bdp = BDr + (size_t)bh * QLEN * KLEN;

    // load Q + r_w_bias (128 rows x 64 halfs = 1024 uint4, 4 per thread)
#pragma unroll
    for (int i = 0; i < 4; i++) {
        int idx = t + 256 * i;
        int r = idx >> 3;            // 0..127
        int c = (idx & 7) * 8;       // 0..56
        uint4 qv = *(const uint4*)(qp + (size_t)(i0 + r) * 24576 + c);
        const __half* qh = (const __half*)&qv;
        float4 b0 = *(const float4*)(rwb + h * 64 + c);
        float4 b1 = *(const float4*)(rwb + h * 64 + c + 4);
        uint4 o = make_uint4(
            f2h2(__half2float(qh[0]) + b0.x, __half2float(qh[1]) + b0.y),
            f2h2(__half2float(qh[2]) + b0.z, __half2float(qh[3]) + b0.w),
            f2h2(__half2float(qh[4]) + b1.x, __half2float(qh[5]) + b1.y),
            f2h2(__half2float(qh[6]) + b1.z, __half2float(qh[7]) + b1.w));
        *(uint4*)&sQ[r * 72 + c] = o;
    }

    const int r0g = i0 + wm + grp;
    const int r1g = r0g + 8;
    float m0 = -3e38f, m1 = -3e38f, l0 = 0.f, l1 = 0.f;
    float oacc[8][4] = {};

    const int njt = (i0 + 640) >> 5;     // rows up to i0+127 attend j <= i+512
    for (int jt = 0; jt < njt; jt++) {
        const int j0 = jt * 32;
        __syncthreads();  // prior readers of sK/sV done (covers sQ on iter 0)
        // load K, V (32 rows x 64 halfs = 256 uint4 each, 1 per thread each)
        {
            int r = t >> 3;          // 0..31
            int c = (t & 7) * 8;     // 0..56
            *(uint4*)&sK[r * 72 + c] = *(const uint4*)(kp + (size_t)(j0 + r) * 24576 + c);
            *(uint4*)&sV[r * 72 + c] = *(const uint4*)(vp + (size_t)(j0 + r) * 24576 + c);
        }
        __syncthreads();

        // AC = Qw . K^T  (warp: 16 rows x 32 cols, K=64 -> 4 ksteps)
        float sacc[4][4] = {};
#pragma unroll
        for (int ks = 0; ks < 4; ks++) {
            unsigned a[4], bf0[4], bf1[4];
            ldsm4(a, &sQ[(wm + l15) * 72 + ks * 16 + lhi]);
            ldsm4(bf0, &sK[l15 * 72 + ks * 16 + lhi]);
            ldsm4(bf1, &sK[(16 + l15) * 72 + ks * 16 + lhi]);
            mma16(sacc[0], a, bf0[0], bf0[2]);
            mma16(sacc[1], a, bf0[1], bf0[3]);
            mma16(sacc[2], a, bf1[0], bf1[2]);
            mma16(sacc[3], a, bf1[1], bf1[3]);
        }

        // gather shifted BDr (fp16), scale, mask
        float sv[4][4];
#pragma unroll
        for (int ni = 0; ni < 4; ni++)
#pragma unroll
            for (int v = 0; v < 4; v++) {
                int jg = j0 + ni * 8 + 2 * tq + (v & 1);
                int ig = (v < 2) ? r0g : r1g;
                float x = -3e38f;
                if (jg <= ig + 512) {
                    float bd = __half2float(__ldg(bdp + (size_t)ig * KLEN + (jg + 511 - ig)));
                    x = (sacc[ni][v] + bd) * 0.125f;
                }
                sv[ni][v] = x;
            }

        // warp-local online softmax
        float rm0 = -3e38f, rm1 = -3e38f;
#pragma unroll
        for (int ni = 0; ni < 4; ni++) {
            rm0 = fmaxf(rm0, fmaxf(sv[ni][0], sv[ni][1]));
            rm1 = fmaxf(rm1, fmaxf(sv[ni][2], sv[ni][3]));
        }
        rm0 = fmaxf(rm0, __shfl_xor_sync(0xffffffff, rm0, 1));
        rm0 = fmaxf(rm0, __shfl_xor_sync(0xffffffff, rm0, 2));
        rm1 = fmaxf(rm1, __shfl_xor_sync(0xffffffff, rm1, 1));
        rm1 = fmaxf(rm1, __shfl_xor_sync(0xffffffff, rm1, 2));
        float mn0 = fmaxf(m0, rm0), mn1 = fmaxf(m1, rm1);
        float c0 = exp2f((m0 - mn0) * 1.44269504f);
        float c1 = exp2f((m1 - mn1) * 1.44269504f);
        float rs0 = 0.f, rs1 = 0.f;
#pragma unroll
        for (int ni = 0; ni < 4; ni++) {
            sv[ni][0] = exp2f((sv[ni][0] - mn0) * 1.44269504f);
            sv[ni][1] = exp2f((sv[ni][1] - mn0) * 1.44269504f);
            sv[ni][2] = exp2f((sv[ni][2] - mn1) * 1.44269504f);
            sv[ni][3] = exp2f((sv[ni][3] - mn1) * 1.44269504f);
            rs0 += sv[ni][0] + sv[ni][1];
            rs1 += sv[ni][2] + sv[ni][3];
        }
        rs0 += __shfl_xor_sync(0xffffffff, rs0, 1);
        rs0 += __shfl_xor_sync(0xffffffff, rs0, 2);
        rs1 += __shfl_xor_sync(0xffffffff, rs1, 1);
        rs1 += __shfl_xor_sync(0xffffffff, rs1, 2);
        l0 = l0 * c0 + rs0;
        l1 = l1 * c1 + rs1;
        m0 = mn0; m1 = mn1;
#pragma unroll
        for (int ni = 0; ni < 8; ni++) {
            oacc[ni][0] *= c0; oacc[ni][1] *= c0;
            oacc[ni][2] *= c1; oacc[ni][3] *= c1;
        }

        // write P (fp16) into sP (warp-private rows; no block barrier needed)
#pragma unroll
        for (int ni = 0; ni < 4; ni++) {
            int col = ni * 8 + 2 * tq;
            *(unsigned*)&sP[(wm + grp) * 40 + col] = f2h2(sv[ni][0], sv[ni][1]);
            *(unsigned*)&sP[(wm + grp + 8) * 40 + col] = f2h2(sv[ni][2], sv[ni][3]);
        }
        __syncwarp();

        // O += P . V  (K=32 -> 2 ksteps; V[j][d] loaded via ldmatrix.trans)
#pragma unroll
        for (int ks = 0; ks < 2; ks++) {
            unsigned a[4];
            ldsm4(a, &sP[(wm + l15) * 40 + ks * 16 + lhi]);
#pragma unroll
            for (int dg = 0; dg < 4; dg++) {
                unsigned bt[4];
                ldsm4t(bt, &sV[(ks * 16 + l15) * 72 + dg * 16 + lhi]);
                mma16(oacc[dg * 2 + 0], a, bt[0], bt[1]);
                mma16(oacc[dg * 2 + 1], a, bt[2], bt[3]);
            }
        }
    }

    // epilogue: normalize and store attn_vec (fp16)
    float inv0 = 1.f / l0, inv1 = 1.f / l1;
#pragma unroll
    for (int ni = 0; ni < 8; ni++) {
        int d = ni * 8 + 2 * tq;
        unsigned h0 = f2h2(oacc[ni][0] * inv0, oacc[ni][1] * inv0);
        unsigned h1v = f2h2(oacc[ni][2] * inv1, oacc[ni][3] * inv1);
        *(unsigned*)(outh + ((size_t)r0g * 8 + b) * 1024 + h * 64 + d) = h0;
        *(unsigned*)(outh + ((size_t)r1g * 8 + b) * 1024 + h * 64 + d) = h1v;
    }
}

// ---------------- residual + layernorm (fp32 out + fp16 copy) ----------------
__global__ __launch_bounds__(256) void resid_ln_kernel(
    const float* __restrict__ x, const float* __restrict__ y,
    const float* __restrict__ g, const float* __restrict__ bta,
    float* __restrict__ out, __half* __restrict__ outh) {
    __shared__ float red[256];
    int row = blockIdx.x, t = threadIdx.x;
    const float* xr = x + (size_t)row * 1024;
    const float* yr = y + (size_t)row * 1024;
    float v[4];
    float s = 0.f;
#pragma unroll
    for (int e = 0; e < 4; e++) {
        int c = t + 256 * e;
        v[e] = xr[c] + yr[c];
        s += v[e];
    }
    red[t] = s;
    __syncthreads();
    for (int w = 128; w > 0; w >>= 1) {
        if (t < w) red[t] += red[t + w];
        __syncthreads();
    }
    float mean = red[0] * (1.f / 1024.f);
    __syncthreads();
    float s2 = 0.f;
#pragma unroll
    for (int e = 0; e < 4; e++) {
        float d = v[e] - mean;
        s2 += d * d;
    }
    red[t] = s2;
    __syncthreads();
    for (int w = 128; w > 0; w >>= 1) {
        if (t < w) red[t] += red[t + w];
        __syncthreads();
    }
    float inv = rsqrtf(red[0] * (1.f / 1024.f) + 1e-5f);
#pragma unroll
    for (int e = 0; e < 4; e++) {
        int c = t + 256 * e;
        float o = (v[e] - mean) * inv * g[c] + bta[c];
        out[(size_t)row * 1024 + c] = o;
        outh[(size_t)row * 1024 + c] = __float2half(o);
    }
}

// ---------------- host orchestration ----------------
extern "C" void kernel_launch(void* const* d_in, const int* in_sizes, int n_in,
                              void* d_out, int out_size) {
    const int* inp = (const int*)d_in[0];
    const float* mems = (const float*)d_in[1];
    const float* emb_table = (const float*)d_in[2];
    const float* r_w_bias = (const float*)d_in[3];
    const float* r_r_bias = (const float*)d_in[4];
    const float* qkv_w = (const float*)d_in[5];
    const float* r_w = (const float*)d_in[6];
    const float* o_w = (const float*)d_in[7];
    const float* ln1_g = (const float*)d_in[8];
    const float* ln1_b = (const float*)d_in[9];
    const float* ff_w1 = (const float*)d_in[10];
    const float* ff_b1 = (const float*)d_in[11];
    const float* ff_w2 = (const float*)d_in[12];
    const float* ff_b2 = (const float*)d_in[13];
    const float* ln2_g = (const float*)d_in[14];
    const float* ln2_b = (const float*)d_in[15];

    void* p;
    cudaGetSymbolAddress(&p, g_core);    float* corep = (float*)p;
    cudaGetSymbolAddress(&p, g_attnout); float* aoutp = (float*)p;
    cudaGetSymbolAddress(&p, g_ff);      float* ffp = (float*)p;
    cudaGetSymbolAddress(&p, g_BDrh);    __half* bdrp = (__half*)p;
    cudaGetSymbolAddress(&p, g_headsh);  __half* headshp = (__half*)p;
    cudaGetSymbolAddress(&p, g_cath);    __half* cathp = (__half*)p;
    cudaGetSymbolAddress(&p, g_pemh);    __half* pemhp = (__half*)p;
    cudaGetSymbolAddress(&p, g_rkh);     __half* rkhp = (__half*)p;
    cudaGetSymbolAddress(&p, g_coreh);   __half* corehp = (__half*)p;
    cudaGetSymbolAddress(&p, g_avech);   __half* avechp = (__half*)p;
    cudaGetSymbolAddress(&p, g_h1h);     __half* h1hp = (__half*)p;
    cudaGetSymbolAddress(&p, g_qkvwh);   __half* qkvwhp = (__half*)p;
    cudaGetSymbolAddress(&p, g_rwh);     __half* rwhp = (__half*)p;
    cudaGetSymbolAddress(&p, g_owh);     __half* owhp = (__half*)p;
    cudaGetSymbolAddress(&p, g_w1h);     __half* w1hp = (__half*)p;
    cudaGetSymbolAddress(&p, g_w2h);     __half* w2hp = (__half*)p;

    const size_t CORE_BYTES = (size_t)QLEN * BSZ * DMODEL * sizeof(float);

    // weight conversions (once per launch)
    {
        int n;
        n = 4 * 3 * DMODEL * DMODEL / 4;
        w2h_kernel<<<n / 256, 256>>>(qkv_w, qkvwhp, n);
        n = 4 * DMODEL * DMODEL / 4;
        w2h_kernel<<<n / 256, 256>>>(r_w, rwhp, n);
        w2h_kernel<<<n / 256, 256>>>(o_w, owhp, n);
        n = 4 * DINNER * DMODEL / 4;
        w2h_kernel<<<n / 256, 256>>>(ff_w1, w1hp, n);
        w2h_kernel<<<n / 256, 256>>>(ff_w2, w2hp, n);
    }

    embed_kernel<<<QLEN * BSZ, 256>>>(inp, emb_table, corep);
    posemb_kernel<<<KLEN, 512>>>(pemhp);

    const __half* qh = headshp + (size_t)MLEN * BSZ * 3 * DMODEL;

    for (int l = 0; l < 4; l++) {
        // cat_h = fp16([mems[l]; core])
        cat_f16_kernel<<<KLEN * BSZ, 256>>>(
            mems + (size_t)l * MLEN * BSZ * DMODEL, corep, cathp);
        // heads = cat @ qkv_w[l]^T   (8192 x 3072 x 1024) fp16 out
        gemm_nt_h<false, false, true><<<dim3(24, 64), 256>>>(
            cathp, qkvwhp + (size_t)l * 3 * DMODEL * DMODEL, nullptr,
            nullptr, headshp, KLEN * BSZ, 3 * DMODEL, DMODEL);
        // rk = pos_emb @ r_w[l]^T    (1024 x 1024 x 1024) fp16 out
        gemm_nt_h<false, false, true><<<dim3(8, 8), 256>>>(
            pemhp, rwhp + (size_t)l * DMODEL * DMODEL, nullptr,
            nullptr, rkhp, KLEN, DMODEL, DMODEL);
        // BDr = (q + r_r_bias) . rk   (fp16 out, dead tiles skipped)
        qk_f16<<<dim3(16, 8, 128), 256>>>(qh, rkhp, r_r_bias, bdrp);
        // flash attention -> avec (fp16)
        flash_attn<<<dim3(4, 128), 256>>>(
            qh, headshp + DMODEL, headshp + 2 * DMODEL, bdrp, r_w_bias, avechp);
        // attn_out = attn_vec @ o_w[l]^T   (4096 x 1024 x 1024) fp32 out
        gemm_nt_h<false, false, false><<<dim3(8, 32), 256>>>(
            avechp, owhp + (size_t)l * DMODEL * DMODEL, nullptr,
            aoutp, nullptr, QLEN * BSZ, DMODEL, DMODEL);
        resid_ln_kernel<<<QLEN * BSZ, 256>>>(corep, aoutp, ln1_g + l * DMODEL,
                                             ln1_b + l * DMODEL, corep, corehp);
        // h1 = relu(core @ ff_w1^T + b1)   (4096 x 4096 x 1024) fp16 out
        gemm_nt_h<true, true, true><<<dim3(32, 32), 256>>>(
            corehp, w1hp + (size_t)l * DINNER * DMODEL, ff_b1 + l * DINNER,
            nullptr, h1hp, QLEN * BSZ, DINNER, DMODEL);
        // ff = h1 @ ff_w2^T + b2           (4096 x 1024 x 4096) fp32 out
        gemm_nt_h<false, true, false><<<dim3(8, 32), 256>>>(
            h1hp, w2hp + (size_t)l * DMODEL * DINNER, ff_b2 + l * DMODEL,
            ffp, nullptr, QLEN * BSZ, DMODEL, DINNER);
        resid_ln_kernel<<<QLEN * BSZ, 256>>>(corep, ffp, ln2_g + l * DMODEL,
                                             ln2_b + l * DMODEL, corep, corehp);
    }

    cudaMemcpyAsync(d_out, corep, CORE_BYTES, cudaMemcpyDeviceToDevice);
}